// round 3
// baseline (speedup 1.0000x reference)
#include <cuda_runtime.h>
#include <math.h>

// Problem constants
#define Dm     256
#define D2     512
#define Sn     128
#define Lh     256
#define NROWS  1024   // (x rows 0..511) + (mouth rows 512..1023); row = m*256 + l
#define HROWS  512

// ---------------- scratch (static __device__, no allocations) ----------------
__device__ float g_XN[NROWS * Dm];     // rmsnormed x|mouth
__device__ float g_P[NROWS * D2];      // inp projection
__device__ float g_XC[NROWS * D2];     // silu(conv(P))
__device__ float g_DELTA[NROWS * D2];  // softplus(fc1)
__device__ float g_BM[NROWS * Sn];     // fc2
__device__ float g_S2[NROWS];          // sum_n Bm^2
__device__ float g_E[4 * Sn * D2];     // E_j[n][d] = A^j * 2^A / j!
__device__ float g_XS[NROWS * D2];     // silu(ssm)
__device__ float g_RES[HROWS * D2];    // silu(Dlin(x_n))
__device__ float g_COMB[HROWS * D2];   // (x_s+m_s)*res

__device__ __forceinline__ float silu_f(float v) { return v / (1.f + expf(-v)); }
__device__ __forceinline__ float softplus_f(float v) {
    return fmaxf(v, 0.f) + log1pf(expf(-fabsf(v)));
}

// ---------------- rmsnorm: 1024 rows of 256 ----------------
__global__ __launch_bounds__(256) void rmsnorm_kernel(
    const float* __restrict__ x, const float* __restrict__ mouth,
    const float* __restrict__ w)
{
    int r = blockIdx.x;
    const float* src = (r < HROWS) ? (x + (size_t)r * Dm)
                                   : (mouth + (size_t)(r - HROWS) * Dm);
    float v = src[threadIdx.x];
    float s = v * v;
    #pragma unroll
    for (int o = 16; o; o >>= 1) s += __shfl_xor_sync(0xffffffffu, s, o);
    __shared__ float ws[8];
    if ((threadIdx.x & 31) == 0) ws[threadIdx.x >> 5] = s;
    __syncthreads();
    float tot = 0.f;
    #pragma unroll
    for (int i = 0; i < 8; i++) tot += ws[i];
    float rms = sqrtf(tot + 1e-5f);
    g_XN[(size_t)r * Dm + threadIdx.x] = v / rms * w[threadIdx.x];
}

// ---------------- generic tiled FP32 GEMM: C = A[MxK] @ W[NxK]^T + bias, act ----
// ACT: 0 none, 1 silu, 2 softplus. All dims multiples of (64,64,16).
template<int ACT>
__global__ __launch_bounds__(256) void gemm_kernel(
    const float* __restrict__ A, const float* __restrict__ W,
    const float* __restrict__ bias, float* __restrict__ C,
    int M, int N, int K)
{
    __shared__ float As[16][64];
    __shared__ float Bs[16][64];
    const int t = threadIdx.x;
    const int tx = t & 15, ty = t >> 4;
    const int row0 = blockIdx.y * 64, col0 = blockIdx.x * 64;
    const int lm = t >> 2, lk = (t & 3) * 4;
    float acc[4][4] = {};
    const float* Ap = A + (size_t)(row0 + lm) * K + lk;
    const float* Wp = W + (size_t)(col0 + lm) * K + lk;

    for (int k0 = 0; k0 < K; k0 += 16) {
        float4 a4 = *(const float4*)(Ap + k0);
        float4 w4 = *(const float4*)(Wp + k0);
        __syncthreads();
        As[lk + 0][lm] = a4.x; As[lk + 1][lm] = a4.y;
        As[lk + 2][lm] = a4.z; As[lk + 3][lm] = a4.w;
        Bs[lk + 0][lm] = w4.x; Bs[lk + 1][lm] = w4.y;
        Bs[lk + 2][lm] = w4.z; Bs[lk + 3][lm] = w4.w;
        __syncthreads();
        #pragma unroll
        for (int kk = 0; kk < 16; kk++) {
            float4 av = *(const float4*)(&As[kk][ty * 4]);
            float4 bv = *(const float4*)(&Bs[kk][tx * 4]);
            float a[4] = {av.x, av.y, av.z, av.w};
            float b[4] = {bv.x, bv.y, bv.z, bv.w};
            #pragma unroll
            for (int i = 0; i < 4; i++)
                #pragma unroll
                for (int j = 0; j < 4; j++)
                    acc[i][j] += a[i] * b[j];
        }
    }
    #pragma unroll
    for (int i = 0; i < 4; i++) {
        int r = row0 + ty * 4 + i;
        #pragma unroll
        for (int j = 0; j < 4; j++) {
            int c = col0 + tx * 4 + j;
            float v = acc[i][j] + bias[c];
            if (ACT == 1) v = silu_f(v);
            else if (ACT == 2) v = softplus_f(v);
            C[(size_t)r * N + c] = v;
        }
    }
}

// ---------------- conv 3x3 SAME over (C=2,H=256,W=512), 2 tensors, + silu ------
__global__ __launch_bounds__(256) void conv_silu_kernel(
    const float* __restrict__ cw, const float* __restrict__ cb)
{
    int h = blockIdx.x;      // 0..255
    int o = blockIdx.y;      // 0..1
    int T = blockIdx.z;      // 0..1 (x / mouth)
    const float* Pb = g_P + (size_t)T * HROWS * D2;
    float wl[2][3][3];
    #pragma unroll
    for (int i = 0; i < 2; i++)
        #pragma unroll
        for (int kh = 0; kh < 3; kh++)
            #pragma unroll
            for (int kw = 0; kw < 3; kw++)
                wl[i][kh][kw] = cw[((o * 2 + i) * 3 + kh) * 3 + kw];
    float b = cb[o];

    for (int w = threadIdx.x; w < D2; w += 256) {
        float acc = b;
        #pragma unroll
        for (int i = 0; i < 2; i++) {
            #pragma unroll
            for (int kh = 0; kh < 3; kh++) {
                int hh = h + kh - 1;
                if (hh < 0 || hh >= Lh) continue;
                const float* rowp = Pb + (size_t)(i * Lh + hh) * D2;
                #pragma unroll
                for (int kw = 0; kw < 3; kw++) {
                    int ww = w + kw - 1;
                    if (ww < 0 || ww >= D2) continue;
                    acc += rowp[ww] * wl[i][kh][kw];
                }
            }
        }
        g_XC[((size_t)T * HROWS + o * Lh + h) * D2 + w] = silu_f(acc);
    }
}

// ---------------- E_j precompute from A: E_j[n][d] = A[d,n]^j * 2^A[d,n] / j! ---
__global__ __launch_bounds__(256) void eprep_kernel(const float* __restrict__ A)
{
    int idx = blockIdx.x * 256 + threadIdx.x;  // d*128 + n, A is [D2][Sn]
    int d = idx >> 7, n = idx & 127;
    float a = A[idx];
    float e0 = exp2f(a);                       // exp(ln2 * a)
    g_E[(0 * Sn + n) * D2 + d] = e0;
    g_E[(1 * Sn + n) * D2 + d] = a * e0;
    g_E[(2 * Sn + n) * D2 + d] = 0.5f * a * a * e0;
    g_E[(3 * Sn + n) * D2 + d] = (1.f / 6.f) * a * a * a * e0;
}

// ---------------- per-row sum of Bm^2 ----------------
__global__ __launch_bounds__(128) void bmstats_kernel()
{
    int r = blockIdx.x;
    float v = g_BM[(size_t)r * Sn + threadIdx.x];
    float s = v * v;
    #pragma unroll
    for (int o = 16; o; o >>= 1) s += __shfl_xor_sync(0xffffffffu, s, o);
    __shared__ float ws[4];
    if ((threadIdx.x & 31) == 0) ws[threadIdx.x >> 5] = s;
    __syncthreads();
    if (threadIdx.x == 0) g_S2[r] = ws[0] + ws[1] + ws[2] + ws[3];
}

// ---------------- SSM: 4-slab GEMM (Bm @ E_j) + Horner epilogue + silu --------
__global__ __launch_bounds__(256) void ssm_kernel()
{
    __shared__ float As[16][64];       // Bm tile [n][row]
    __shared__ float Es[4][16][64];    // E_j tiles [n][d]
    const int t = threadIdx.x;
    const int tx = t & 15, ty = t >> 4;
    const int row0 = blockIdx.y * 64, col0 = blockIdx.x * 64;
    const int lm = t >> 2, lk = (t & 3) * 4;
    const int en = t >> 4, ed = (t & 15) * 4;
    float acc[4][4][4] = {};  // [term][rowfrag][colfrag]

    for (int k0 = 0; k0 < Sn; k0 += 16) {
        float4 a4 = *(const float4*)(&g_BM[(size_t)(row0 + lm) * Sn + k0 + lk]);
        float4 e4[4];
        #pragma unroll
        for (int j = 0; j < 4; j++)
            e4[j] = *(const float4*)(&g_E[(size_t)(j * Sn + k0 + en) * D2 + col0 + ed]);
        __syncthreads();
        As[lk + 0][lm] = a4.x; As[lk + 1][lm] = a4.y;
        As[lk + 2][lm] = a4.z; As[lk + 3][lm] = a4.w;
        #pragma unroll
        for (int j = 0; j < 4; j++)
            *(float4*)(&Es[j][en][ed]) = e4[j];
        __syncthreads();
        #pragma unroll
        for (int kk = 0; kk < 16; kk++) {
            float4 av = *(const float4*)(&As[kk][ty * 4]);
            float a[4] = {av.x, av.y, av.z, av.w};
            #pragma unroll
            for (int j = 0; j < 4; j++) {
                float4 ev = *(const float4*)(&Es[j][kk][tx * 4]);
                float e[4] = {ev.x, ev.y, ev.z, ev.w};
                #pragma unroll
                for (int i = 0; i < 4; i++)
                    #pragma unroll
                    for (int c = 0; c < 4; c++)
                        acc[j][i][c] += a[i] * e[c];
            }
        }
    }

    #pragma unroll
    for (int i = 0; i < 4; i++) {
        int r = row0 + ty * 4 + i;
        float s2 = g_S2[r];
        #pragma unroll
        for (int c = 0; c < 4; c++) {
            int d = col0 + tx * 4 + c;
            float dl = g_DELTA[(size_t)r * D2 + d];
            float u = dl - 0.69314718055994531f;
            float s = acc[0][i][c]
                    + u * (acc[1][i][c] + u * (acc[2][i][c] + u * acc[3][i][c]));
            s += g_XC[(size_t)r * D2 + d] * dl * s2;
            g_XS[(size_t)r * D2 + d] = silu_f(s);
        }
    }
}

// ---------------- comb = (x_s + m_s) * res ----------------
__global__ __launch_bounds__(256) void comb_kernel()
{
    int idx = blockIdx.x * 256 + threadIdx.x;  // < 512*512
    g_COMB[idx] = (g_XS[idx] + g_XS[idx + HROWS * D2]) * g_RES[idx];
}

// ---------------- launch ----------------
extern "C" void kernel_launch(void* const* d_in, const int* in_sizes, int n_in,
                              void* d_out, int out_size)
{
    const float* x      = (const float*)d_in[0];
    const float* mouth  = (const float*)d_in[1];
    const float* norm_w = (const float*)d_in[2];
    const float* inp_W  = (const float*)d_in[3];
    const float* inp_b  = (const float*)d_in[4];
    const float* out_W  = (const float*)d_in[5];
    const float* out_b  = (const float*)d_in[6];
    const float* Dlin_W = (const float*)d_in[7];
    const float* Dlin_b = (const float*)d_in[8];
    const float* conv_W = (const float*)d_in[9];
    const float* conv_b = (const float*)d_in[10];
    const float* fc1_W  = (const float*)d_in[11];
    const float* fc1_b  = (const float*)d_in[12];
    const float* fc2_W  = (const float*)d_in[13];
    const float* fc2_b  = (const float*)d_in[14];
    const float* A      = (const float*)d_in[15];

    float *pXN, *pP, *pXC, *pDELTA, *pBM, *pRES, *pCOMB;
    cudaGetSymbolAddress((void**)&pXN,    g_XN);
    cudaGetSymbolAddress((void**)&pP,     g_P);
    cudaGetSymbolAddress((void**)&pXC,    g_XC);
    cudaGetSymbolAddress((void**)&pDELTA, g_DELTA);
    cudaGetSymbolAddress((void**)&pBM,    g_BM);
    cudaGetSymbolAddress((void**)&pRES,   g_RES);
    cudaGetSymbolAddress((void**)&pCOMB,  g_COMB);

    // E slabs (independent of everything else)
    eprep_kernel<<<256, 256>>>(A);
    // rmsnorm both tensors
    rmsnorm_kernel<<<NROWS, 256>>>(x, mouth, norm_w);
    // inp projection: P = XN @ inp_W^T + inp_b   [1024x512]
    gemm_kernel<0><<<dim3(D2 / 64, NROWS / 64), 256>>>(pXN, inp_W, inp_b, pP,
                                                       NROWS, D2, Dm);
    // conv + silu -> XC
    conv_silu_kernel<<<dim3(Lh, 2, 2), 256>>>(conv_W, conv_b);
    // delta = softplus(XC @ fc1^T + b)   [1024x512]
    gemm_kernel<2><<<dim3(D2 / 64, NROWS / 64), 256>>>(pXC, fc1_W, fc1_b, pDELTA,
                                                       NROWS, D2, D2);
    // Bm = XC @ fc2^T + b   [1024x128]
    gemm_kernel<0><<<dim3(Sn / 64, NROWS / 64), 256>>>(pXC, fc2_W, fc2_b, pBM,
                                                       NROWS, Sn, D2);
    // per-row sum Bm^2
    bmstats_kernel<<<NROWS, 128>>>();
    // ssm (4-slab GEMM + Horner + silu) -> XS
    ssm_kernel<<<dim3(D2 / 64, NROWS / 64), 256>>>();
    // res = silu(XN[x rows] @ Dlin^T + b)   [512x512]
    gemm_kernel<1><<<dim3(D2 / 64, HROWS / 64), 256>>>(pXN, Dlin_W, Dlin_b, pRES,
                                                       HROWS, D2, Dm);
    // comb
    comb_kernel<<<(HROWS * D2) / 256, 256>>>();
    // out = COMB @ out_W^T + out_b   [512x256]
    gemm_kernel<0><<<dim3(Dm / 64, HROWS / 64), 256>>>(pCOMB, out_W, out_b,
                                                       (float*)d_out,
                                                       HROWS, Dm, D2);
}

// round 6
// speedup vs baseline: 1.7513x; 1.7513x over previous
#include <cuda_runtime.h>
#include <math.h>
#include <stdint.h>

// Problem constants
#define Dm     256
#define D2     512
#define Sn     128
#define Lh     256
#define NROWS  1024   // (x rows 0..511) + (mouth rows 512..1023); row = m*256 + l
#define HROWS  512
#define LN2F   0.69314718055994531f

// ---------------- scratch (static __device__, no allocations) ----------------
__device__ float g_XN[NROWS * Dm];     // rmsnormed x|mouth
__device__ float g_P[NROWS * D2];      // inp projection
__device__ float g_XC[NROWS * D2];     // silu(conv(P))
__device__ float g_DELTA[NROWS * D2];  // softplus(fc1)
__device__ float g_BM[NROWS * Sn];     // fc2
__device__ float g_E[4 * D2 * Sn];     // E_j[d][n] = A^j * 2^A / j!   (d-major)
__device__ float g_XS[NROWS * D2];     // silu(ssm)
__device__ float g_RES[HROWS * D2];    // silu(Dlin(x_n))

__device__ __forceinline__ float silu_f(float v) { return v / (1.f + expf(-v)); }
__device__ __forceinline__ float softplus_f(float v) {
    return fmaxf(v, 0.f) + log1pf(expf(-fabsf(v)));
}
__device__ __forceinline__ uint32_t f2tf32(float x) {
    uint32_t r;
    asm("cvt.rna.tf32.f32 %0, %1;" : "=r"(r) : "f"(x));
    return r;
}
__device__ __forceinline__ float4 tf32x4(float4 v) {
    v.x = __uint_as_float(f2tf32(v.x));
    v.y = __uint_as_float(f2tf32(v.y));
    v.z = __uint_as_float(f2tf32(v.z));
    v.w = __uint_as_float(f2tf32(v.w));
    return v;
}
__device__ __forceinline__ void mma_tf32(float c[4],
    uint32_t a0, uint32_t a1, uint32_t a2, uint32_t a3,
    uint32_t b0, uint32_t b1)
{
    asm("mma.sync.aligned.m16n8k8.row.col.f32.tf32.tf32.f32 "
        "{%0,%1,%2,%3}, {%4,%5,%6,%7}, {%8,%9}, {%0,%1,%2,%3};"
        : "+f"(c[0]), "+f"(c[1]), "+f"(c[2]), "+f"(c[3])
        : "r"(a0), "r"(a1), "r"(a2), "r"(a3), "r"(b0), "r"(b1));
}

// ---------------- rmsnorm: 1024 rows of 256 ----------------
__global__ __launch_bounds__(256) void rmsnorm_kernel(
    const float* __restrict__ x, const float* __restrict__ mouth,
    const float* __restrict__ w)
{
    int r = blockIdx.x;
    const float* src = (r < HROWS) ? (x + (size_t)r * Dm)
                                   : (mouth + (size_t)(r - HROWS) * Dm);
    float v = src[threadIdx.x];
    float s = v * v;
    #pragma unroll
    for (int o = 16; o; o >>= 1) s += __shfl_xor_sync(0xffffffffu, s, o);
    __shared__ float ws[8];
    if ((threadIdx.x & 31) == 0) ws[threadIdx.x >> 5] = s;
    __syncthreads();
    float tot = 0.f;
    #pragma unroll
    for (int i = 0; i < 8; i++) tot += ws[i];
    float rms = sqrtf(tot + 1e-5f);
    g_XN[(size_t)r * Dm + threadIdx.x] = v / rms * w[threadIdx.x];
}

// ---------------- E_j precompute: g_E[(j*D2 + d)*Sn + n] ----------------
__global__ __launch_bounds__(256) void eprep_kernel(const float* __restrict__ A)
{
    int idx = blockIdx.x * 256 + threadIdx.x;  // d*128 + n, A is [D2][Sn]
    float a = A[idx];
    float e0 = exp2f(a);  // exp(ln2 * a)
    g_E[0 * D2 * Sn + idx] = e0;
    g_E[1 * D2 * Sn + idx] = a * e0;
    g_E[2 * D2 * Sn + idx] = 0.5f * a * a * e0;
    g_E[3 * D2 * Sn + idx] = (1.f / 6.f) * a * a * a * e0;
}

// ---------------- tf32 tensor-core GEMM: C = A[MxK] @ W[NxK]^T + bias --------
// 64x64 block tile, BK=32, 4 warps (32x32 warp tile), m16n8k8 tf32 mma.
// ACT: 0 none, 1 silu, 2 softplus. FUSE_COMB: A := (A + A2) * A3 elementwise.
// M,N multiples of 64; K multiple of 32.
template<int ACT, int FUSE_COMB>
__global__ __launch_bounds__(128) void gemm_tf32_kernel(
    const float* __restrict__ A, const float* __restrict__ W,
    const float* __restrict__ bias, float* __restrict__ C,
    int M, int N, int K,
    const float* __restrict__ A2, const float* __restrict__ A3)
{
    __shared__ float As[64 * 36];
    __shared__ float Bs[64 * 36];
    const int t = threadIdx.x;
    const int lane = t & 31, warp = t >> 5;
    const int wm = warp >> 1, wn = warp & 1;         // 2x2 warp grid
    const int g = lane >> 2, tig = lane & 3;
    const int row0 = blockIdx.y * 64, col0 = blockIdx.x * 64;
    const int lr = t >> 3;        // 0..15 (tile row, step 16)
    const int lc = t & 7;         // float4 column within BK=32

    const float4* Ag = (const float4*)(A + (size_t)(row0 + lr) * K) + lc;
    const float4* Wg = (const float4*)(W + (size_t)(col0 + lr) * K) + lc;
    const float4* A2g = FUSE_COMB ? (const float4*)(A2 + (size_t)(row0 + lr) * K) + lc : (const float4*)0;
    const float4* A3g = FUSE_COMB ? (const float4*)(A3 + (size_t)(row0 + lr) * K) + lc : (const float4*)0;
    const size_t rstep = (size_t)4 * K;  // 16 rows in float4 units

    float c[2][4][4];
    #pragma unroll
    for (int i = 0; i < 2; i++)
        #pragma unroll
        for (int j = 0; j < 4; j++)
            #pragma unroll
            for (int q = 0; q < 4; q++) c[i][j][q] = 0.f;

    const int ntiles = K >> 5;
    float4 abuf[4], wbuf[4];
    #pragma unroll
    for (int i = 0; i < 4; i++) {
        abuf[i] = Ag[i * rstep];
        if (FUSE_COMB) {
            float4 x2 = A2g[i * rstep], x3 = A3g[i * rstep];
            abuf[i].x = (abuf[i].x + x2.x) * x3.x;
            abuf[i].y = (abuf[i].y + x2.y) * x3.y;
            abuf[i].z = (abuf[i].z + x2.z) * x3.z;
            abuf[i].w = (abuf[i].w + x2.w) * x3.w;
        }
        wbuf[i] = Wg[i * rstep];
    }

    for (int kt = 0; kt < ntiles; kt++) {
        __syncthreads();
        #pragma unroll
        for (int i = 0; i < 4; i++) {
            *(float4*)&As[(lr + i * 16) * 36 + lc * 4] = tf32x4(abuf[i]);
            *(float4*)&Bs[(lr + i * 16) * 36 + lc * 4] = tf32x4(wbuf[i]);
        }
        __syncthreads();
        if (kt + 1 < ntiles) {
            int ko = (kt + 1) * 8;
            #pragma unroll
            for (int i = 0; i < 4; i++) {
                abuf[i] = Ag[i * rstep + ko];
                if (FUSE_COMB) {
                    float4 x2 = A2g[i * rstep + ko], x3 = A3g[i * rstep + ko];
                    abuf[i].x = (abuf[i].x + x2.x) * x3.x;
                    abuf[i].y = (abuf[i].y + x2.y) * x3.y;
                    abuf[i].z = (abuf[i].z + x2.z) * x3.z;
                    abuf[i].w = (abuf[i].w + x2.w) * x3.w;
                }
                wbuf[i] = Wg[i * rstep + ko];
            }
        }
        #pragma unroll
        for (int k8 = 0; k8 < 4; k8++) {
            const int kb = k8 * 8;
            uint32_t afr[2][4], bfr[4][2];
            #pragma unroll
            for (int mi = 0; mi < 2; mi++) {
                int r = wm * 32 + mi * 16 + g;
                afr[mi][0] = __float_as_uint(As[r * 36 + kb + tig]);
                afr[mi][1] = __float_as_uint(As[(r + 8) * 36 + kb + tig]);
                afr[mi][2] = __float_as_uint(As[r * 36 + kb + tig + 4]);
                afr[mi][3] = __float_as_uint(As[(r + 8) * 36 + kb + tig + 4]);
            }
            #pragma unroll
            for (int ni = 0; ni < 4; ni++) {
                int n = wn * 32 + ni * 8 + g;
                bfr[ni][0] = __float_as_uint(Bs[n * 36 + kb + tig]);
                bfr[ni][1] = __float_as_uint(Bs[n * 36 + kb + tig + 4]);
            }
            #pragma unroll
            for (int mi = 0; mi < 2; mi++)
                #pragma unroll
                for (int ni = 0; ni < 4; ni++)
                    mma_tf32(c[mi][ni], afr[mi][0], afr[mi][1], afr[mi][2],
                             afr[mi][3], bfr[ni][0], bfr[ni][1]);
        }
    }

    // epilogue
    #pragma unroll
    for (int mi = 0; mi < 2; mi++) {
        int r = row0 + wm * 32 + mi * 16 + g;
        #pragma unroll
        for (int ni = 0; ni < 4; ni++) {
            int n = col0 + wn * 32 + ni * 8 + 2 * tig;
            float b0 = bias[n], b1 = bias[n + 1];
            float v0 = c[mi][ni][0] + b0, v1 = c[mi][ni][1] + b1;
            float v2 = c[mi][ni][2] + b0, v3 = c[mi][ni][3] + b1;
            if (ACT == 1) { v0 = silu_f(v0); v1 = silu_f(v1); v2 = silu_f(v2); v3 = silu_f(v3); }
            else if (ACT == 2) { v0 = softplus_f(v0); v1 = softplus_f(v1); v2 = softplus_f(v2); v3 = softplus_f(v3); }
            *(float2*)&C[(size_t)r * N + n] = make_float2(v0, v1);
            *(float2*)&C[(size_t)(r + 8) * N + n] = make_float2(v2, v3);
        }
    }
}

// ---------------- conv 3x3 SAME, both out channels per block + silu ----------
__global__ __launch_bounds__(256) void conv_silu_kernel(
    const float* __restrict__ cw, const float* __restrict__ cb)
{
    const int h = blockIdx.x;      // 0..255
    const int T = blockIdx.y;      // 0..1 (x / mouth)
    __shared__ float rows[2][3][516];
    __shared__ float wsh[36];
    __shared__ float bsh[2];
    const int t = threadIdx.x;
    if (t < 36) wsh[t] = cw[t];    // [o][i][kh][kw]
    if (t < 2) bsh[t] = cb[t];
    const float* Pb = g_P + (size_t)T * HROWS * D2;

    for (int idx = t; idx < 2 * 3 * 128; idx += 256) {
        int i = idx / 384;
        int rem = idx - i * 384;
        int r = rem >> 7;
        int c4 = rem & 127;
        int hh = h + r - 1;
        float4 v = make_float4(0.f, 0.f, 0.f, 0.f);
        if (hh >= 0 && hh < Lh)
            v = ((const float4*)(Pb + (size_t)(i * Lh + hh) * D2))[c4];
        *(float4*)&rows[i][r][c4 * 4] = v;
    }
    __syncthreads();

    #pragma unroll
    for (int ws = 0; ws < 2; ws++) {
        int w = t + ws * 256;
        float acc0 = bsh[0], acc1 = bsh[1];
        #pragma unroll
        for (int i = 0; i < 2; i++)
            #pragma unroll
            for (int kh = 0; kh < 3; kh++) {
                float dl = (w == 0)       ? 0.f : rows[i][kh][w - 1];
                float dc = rows[i][kh][w];
                float dr = (w == D2 - 1)  ? 0.f : rows[i][kh][w + 1];
                acc0 += dl * wsh[i * 9 + kh * 3 + 0]
                      + dc * wsh[i * 9 + kh * 3 + 1]
                      + dr * wsh[i * 9 + kh * 3 + 2];
                acc1 += dl * wsh[18 + i * 9 + kh * 3 + 0]
                      + dc * wsh[18 + i * 9 + kh * 3 + 1]
                      + dr * wsh[18 + i * 9 + kh * 3 + 2];
            }
        g_XC[((size_t)T * HROWS + 0 * Lh + h) * D2 + w] = silu_f(acc0);
        g_XC[((size_t)T * HROWS + 1 * Lh + h) * D2 + w] = silu_f(acc1);
    }
}

// ---------------- SSM: 4-slab tf32 GEMM + S2 + Horner + silu -----------------
// C_j = Bm[1024x128] @ E_j[128 x D2]; grid (D2/64, NROWS/64), 128 threads.
__global__ __launch_bounds__(128) void ssm_tf32_kernel()
{
    __shared__ float As[64 * 36];
    __shared__ float Es[4][64 * 36];
    __shared__ float s2s[64];
    const int t = threadIdx.x;
    const int lane = t & 31, warp = t >> 5;
    const int wm = warp >> 1, wn = warp & 1;
    const int g = lane >> 2, tig = lane & 3;
    const int row0 = blockIdx.y * 64, col0 = blockIdx.x * 64;
    const int lr = t >> 3, lc = t & 7;

    if (t < 64) s2s[t] = 0.f;
    // per-row sum of Bm^2: 2 threads per row, 64 elems each
    float s2p = 0.f;
    {
        const float4* bm4 = (const float4*)(g_BM + (size_t)(row0 + (t >> 1)) * Sn
                                            + (t & 1) * 64);
        #pragma unroll
        for (int i = 0; i < 16; i++) {
            float4 v = bm4[i];
            s2p += v.x * v.x + v.y * v.y + v.z * v.z + v.w * v.w;
        }
    }
    __syncthreads();
    atomicAdd(&s2s[t >> 1], s2p);

    float c[4][2][4][4];
    #pragma unroll
    for (int j = 0; j < 4; j++)
        #pragma unroll
        for (int mi = 0; mi < 2; mi++)
            #pragma unroll
            for (int ni = 0; ni < 4; ni++)
                #pragma unroll
                for (int q = 0; q < 4; q++) c[j][mi][ni][q] = 0.f;

    for (int kt = 0; kt < 4; kt++) {
        __syncthreads();
        #pragma unroll
        for (int i = 0; i < 4; i++) {
            float4 v = *(const float4*)(g_BM + (size_t)(row0 + lr + i * 16) * Sn
                                        + kt * 32 + lc * 4);
            *(float4*)&As[(lr + i * 16) * 36 + lc * 4] = tf32x4(v);
        }
        #pragma unroll
        for (int j = 0; j < 4; j++)
            #pragma unroll
            for (int i = 0; i < 4; i++) {
                float4 v = *(const float4*)(g_E + (size_t)(j * D2 + col0 + lr + i * 16) * Sn
                                            + kt * 32 + lc * 4);
                *(float4*)&Es[j][(lr + i * 16) * 36 + lc * 4] = tf32x4(v);
            }
        __syncthreads();
        #pragma unroll
        for (int k8 = 0; k8 < 4; k8++) {
            const int kb = k8 * 8;
            uint32_t afr[2][4];
            #pragma unroll
            for (int mi = 0; mi < 2; mi++) {
                int r = wm * 32 + mi * 16 + g;
                afr[mi][0] = __float_as_uint(As[r * 36 + kb + tig]);
                afr[mi][1] = __float_as_uint(As[(r + 8) * 36 + kb + tig]);
                afr[mi][2] = __float_as_uint(As[r * 36 + kb + tig + 4]);
                afr[mi][3] = __float_as_uint(As[(r + 8) * 36 + kb + tig + 4]);
            }
            #pragma unroll
            for (int j = 0; j < 4; j++) {
                uint32_t bfr[4][2];
                #pragma unroll
                for (int ni = 0; ni < 4; ni++) {
                    int n = wn * 32 + ni * 8 + g;
                    bfr[ni][0] = __float_as_uint(Es[j][n * 36 + kb + tig]);
                    bfr[ni][1] = __float_as_uint(Es[j][n * 36 + kb + tig + 4]);
                }
                #pragma unroll
                for (int mi = 0; mi < 2; mi++)
                    #pragma unroll
                    for (int ni = 0; ni < 4; ni++)
                        mma_tf32(c[j][mi][ni], afr[mi][0], afr[mi][1], afr[mi][2],
                                 afr[mi][3], bfr[ni][0], bfr[ni][1]);
            }
        }
    }
    __syncthreads();

    // epilogue: Horner in u + x*delta*S2, then silu
    #pragma unroll
    for (int mi = 0; mi < 2; mi++) {
        #pragma unroll
        for (int half = 0; half < 2; half++) {
            int rl = wm * 32 + mi * 16 + g + half * 8;
            int r = row0 + rl;
            float s2 = s2s[rl];
            #pragma unroll
            for (int ni = 0; ni < 4; ni++) {
                int d = col0 + wn * 32 + ni * 8 + 2 * tig;
                float2 dl = *(const float2*)&g_DELTA[(size_t)r * D2 + d];
                float2 xc = *(const float2*)&g_XC[(size_t)r * D2 + d];
                int q0 = half * 2;      // 0 or 2
                float u0 = dl.x - LN2F, u1 = dl.y - LN2F;
                float s0 = c[0][mi][ni][q0]
                         + u0 * (c[1][mi][ni][q0] + u0 * (c[2][mi][ni][q0] + u0 * c[3][mi][ni][q0]));
                float s1 = c[0][mi][ni][q0 + 1]
                         + u1 * (c[1][mi][ni][q0 + 1] + u1 * (c[2][mi][ni][q0 + 1] + u1 * c[3][mi][ni][q0 + 1]));
                s0 += xc.x * dl.x * s2;
                s1 += xc.y * dl.y * s2;
                *(float2*)&g_XS[(size_t)r * D2 + d] = make_float2(silu_f(s0), silu_f(s1));
            }
        }
    }
}

// ---------------- launch ----------------
extern "C" void kernel_launch(void* const* d_in, const int* in_sizes, int n_in,
                              void* d_out, int out_size)
{
    const float* x      = (const float*)d_in[0];
    const float* mouth  = (const float*)d_in[1];
    const float* norm_w = (const float*)d_in[2];
    const float* inp_W  = (const float*)d_in[3];
    const float* inp_b  = (const float*)d_in[4];
    const float* out_W  = (const float*)d_in[5];
    const float* out_b  = (const float*)d_in[6];
    const float* Dlin_W = (const float*)d_in[7];
    const float* Dlin_b = (const float*)d_in[8];
    const float* conv_W = (const float*)d_in[9];
    const float* conv_b = (const float*)d_in[10];
    const float* fc1_W  = (const float*)d_in[11];
    const float* fc1_b  = (const float*)d_in[12];
    const float* fc2_W  = (const float*)d_in[13];
    const float* fc2_b  = (const float*)d_in[14];
    const float* A      = (const float*)d_in[15];

    float *pXN, *pP, *pXC, *pDELTA, *pBM, *pRES, *pXS;
    cudaGetSymbolAddress((void**)&pXN,    g_XN);
    cudaGetSymbolAddress((void**)&pP,     g_P);
    cudaGetSymbolAddress((void**)&pXC,    g_XC);
    cudaGetSymbolAddress((void**)&pDELTA, g_DELTA);
    cudaGetSymbolAddress((void**)&pBM,    g_BM);
    cudaGetSymbolAddress((void**)&pRES,   g_RES);
    cudaGetSymbolAddress((void**)&pXS,    g_XS);

    // E slabs (independent of everything else)
    eprep_kernel<<<(D2 * Sn) / 256, 256>>>(A);
    // rmsnorm both tensors
    rmsnorm_kernel<<<NROWS, 256>>>(x, mouth, norm_w);
    // inp projection: P = XN @ inp_W^T + inp_b   [1024x512]
    gemm_tf32_kernel<0, 0><<<dim3(D2 / 64, NROWS / 64), 128>>>(
        pXN, inp_W, inp_b, pP, NROWS, D2, Dm, nullptr, nullptr);
    // conv + silu -> XC
    conv_silu_kernel<<<dim3(Lh, 2), 256>>>(conv_W, conv_b);
    // delta = softplus(XC @ fc1^T + b)   [1024x512]
    gemm_tf32_kernel<2, 0><<<dim3(D2 / 64, NROWS / 64), 128>>>(
        pXC, fc1_W, fc1_b, pDELTA, NROWS, D2, D2, nullptr, nullptr);
    // Bm = XC @ fc2^T + b   [1024x128]
    gemm_tf32_kernel<0, 0><<<dim3(Sn / 64, NROWS / 64), 128>>>(
        pXC, fc2_W, fc2_b, pBM, NROWS, Sn, D2, nullptr, nullptr);
    // ssm: 4-slab GEMM + S2 + Horner + silu -> XS
    ssm_tf32_kernel<<<dim3(D2 / 64, NROWS / 64), 128>>>();
    // res = silu(XN[x rows] @ Dlin^T + b)   [512x512]
    gemm_tf32_kernel<1, 0><<<dim3(D2 / 64, HROWS / 64), 128>>>(
        pXN, Dlin_W, Dlin_b, pRES, HROWS, D2, Dm, nullptr, nullptr);
    // out = ((XS_x + XS_m) * RES) @ out_W^T + out_b   [512x256], comb fused
    gemm_tf32_kernel<0, 1><<<dim3(Dm / 64, HROWS / 64), 128>>>(
        pXS, out_W, out_b, (float*)d_out, HROWS, Dm, D2,
        pXS + (size_t)HROWS * D2, pRES);
}

// round 7
// speedup vs baseline: 2.0514x; 1.1713x over previous
#include <cuda_runtime.h>
#include <math.h>
#include <stdint.h>

// Problem constants
#define Dm     256
#define D2     512
#define Sn     128
#define Lh     256
#define NROWS  1024   // (x rows 0..511) + (mouth rows 512..1023)
#define HROWS  512
#define LN2F   0.69314718055994531f

// ---------------- scratch (static __device__, no allocations) ----------------
__device__ float g_RMS[NROWS];         // 1/sqrt(sum x^2 + eps) per row
__device__ float g_P[NROWS * D2];      // inp projection
__device__ float g_XC[NROWS * D2];     // silu(conv(P))
__device__ float g_DELTA[NROWS * D2];  // softplus(fc1)
__device__ float g_BM[NROWS * Sn];     // fc2
__device__ float g_E[4 * D2 * Sn];     // E_j[d][n] = A^j * 2^A / j!  (d-major)
__device__ float g_XS[NROWS * D2];     // silu(ssm)
__device__ float g_RES[HROWS * D2];    // silu(Dlin(x_n))

__device__ __forceinline__ float silu_f(float v) { return v / (1.f + expf(-v)); }
__device__ __forceinline__ float softplus_f(float v) {
    return fmaxf(v, 0.f) + log1pf(expf(-fabsf(v)));
}
__device__ __forceinline__ uint32_t f2tf32(float x) {
    uint32_t r;
    asm("cvt.rna.tf32.f32 %0, %1;" : "=r"(r) : "f"(x));
    return r;
}
__device__ __forceinline__ float4 tf32x4(float4 v) {
    v.x = __uint_as_float(f2tf32(v.x));
    v.y = __uint_as_float(f2tf32(v.y));
    v.z = __uint_as_float(f2tf32(v.z));
    v.w = __uint_as_float(f2tf32(v.w));
    return v;
}
__device__ __forceinline__ void mma_tf32(float c[4],
    uint32_t a0, uint32_t a1, uint32_t a2, uint32_t a3,
    uint32_t b0, uint32_t b1)
{
    asm("mma.sync.aligned.m16n8k8.row.col.f32.tf32.tf32.f32 "
        "{%0,%1,%2,%3}, {%4,%5,%6,%7}, {%8,%9}, {%0,%1,%2,%3};"
        : "+f"(c[0]), "+f"(c[1]), "+f"(c[2]), "+f"(c[3])
        : "r"(a0), "r"(a1), "r"(a2), "r"(a3), "r"(b0), "r"(b1));
}

// ---------------- prep: per-row 1/rms (blocks 0..127) + E slabs (128..383) ----
__global__ __launch_bounds__(256) void prep_kernel(
    const float* __restrict__ x, const float* __restrict__ mouth,
    const float* __restrict__ A)
{
    const int bid = blockIdx.x, t = threadIdx.x;
    if (bid < 128) {
        // 8 warps/block, one warp per row
        int warp = t >> 5, lane = t & 31;
        int r = bid * 8 + warp;
        const float* src = (r < HROWS) ? (x + (size_t)r * Dm)
                                       : (mouth + (size_t)(r - HROWS) * Dm);
        float4 v0 = ((const float4*)src)[lane * 2];
        float4 v1 = ((const float4*)src)[lane * 2 + 1];
        float s = v0.x * v0.x + v0.y * v0.y + v0.z * v0.z + v0.w * v0.w
                + v1.x * v1.x + v1.y * v1.y + v1.z * v1.z + v1.w * v1.w;
        #pragma unroll
        for (int o = 16; o; o >>= 1) s += __shfl_xor_sync(0xffffffffu, s, o);
        if (lane == 0) g_RMS[r] = 1.f / sqrtf(s + 1e-5f);
    } else {
        int idx = (bid - 128) * 256 + t;   // d*128 + n, A is [D2][Sn]
        float a = A[idx];
        float e0 = exp2f(a);               // exp(ln2 * a)
        g_E[0 * D2 * Sn + idx] = e0;
        g_E[1 * D2 * Sn + idx] = a * e0;
        g_E[2 * D2 * Sn + idx] = 0.5f * a * a * e0;
        g_E[3 * D2 * Sn + idx] = (1.f / 6.f) * a * a * a * e0;
    }
}

// ---------------- tf32 GEMM core: C = A[.x64 x K] @ W[NxK]^T + bias ----------
// 64x64 block tile, BK=32, 4 warps, m16n8k8. A_t points at the tile's row 0.
// AMODE 0: plain; 1: a * wvec[col] * rinv[row]; 2: (a + a2)*a3 (comb).
// ACT 0 none, 1 silu, 2 softplus.
template<int ACT, int AMODE>
__device__ __forceinline__ void gemm_core(
    float* sm,
    const float* __restrict__ A_t, const float* __restrict__ W,
    const float* __restrict__ bias, float* __restrict__ C,
    int N, int K, int row0, int col0,
    const float* __restrict__ rinv, const float* __restrict__ wvec,
    const float* __restrict__ A2_t, const float* __restrict__ A3_t)
{
    float* As = sm;
    float* Bs = sm + 64 * 36;
    const int t = threadIdx.x;
    const int lane = t & 31, warp = t >> 5;
    const int wm = warp >> 1, wn = warp & 1;        // 2x2 warp grid
    const int g = lane >> 2, tig = lane & 3;
    const int lr = t >> 3;        // 0..15
    const int lc = t & 7;         // float4 col within BK=32

    const float4* Ag = (const float4*)(A_t + (size_t)lr * K) + lc;
    const float4* Wg = (const float4*)(W + (size_t)(col0 + lr) * K) + lc;
    const float4* A2g = (AMODE == 2) ? (const float4*)(A2_t + (size_t)lr * K) + lc : (const float4*)0;
    const float4* A3g = (AMODE == 2) ? (const float4*)(A3_t + (size_t)lr * K) + lc : (const float4*)0;
    const size_t rstep = (size_t)4 * K;  // 16 rows in float4 units

    float rv[4];
    if (AMODE == 1) {
        #pragma unroll
        for (int i = 0; i < 4; i++) rv[i] = rinv[row0 + lr + i * 16];
    }

    float c[2][4][4];
    #pragma unroll
    for (int i = 0; i < 2; i++)
        #pragma unroll
        for (int j = 0; j < 4; j++)
            #pragma unroll
            for (int q = 0; q < 4; q++) c[i][j][q] = 0.f;

    const int ntiles = K >> 5;
    float4 abuf[4], wbuf[4];
    float4 wv4;
    if (AMODE == 1) wv4 = ((const float4*)wvec)[lc];
    #pragma unroll
    for (int i = 0; i < 4; i++) {
        abuf[i] = Ag[i * rstep];
        if (AMODE == 1) {
            abuf[i].x *= wv4.x * rv[i]; abuf[i].y *= wv4.y * rv[i];
            abuf[i].z *= wv4.z * rv[i]; abuf[i].w *= wv4.w * rv[i];
        } else if (AMODE == 2) {
            float4 x2 = A2g[i * rstep], x3 = A3g[i * rstep];
            abuf[i].x = (abuf[i].x + x2.x) * x3.x;
            abuf[i].y = (abuf[i].y + x2.y) * x3.y;
            abuf[i].z = (abuf[i].z + x2.z) * x3.z;
            abuf[i].w = (abuf[i].w + x2.w) * x3.w;
        }
        wbuf[i] = Wg[i * rstep];
    }

    for (int kt = 0; kt < ntiles; kt++) {
        __syncthreads();
        #pragma unroll
        for (int i = 0; i < 4; i++) {
            *(float4*)&As[(lr + i * 16) * 36 + lc * 4] = tf32x4(abuf[i]);
            *(float4*)&Bs[(lr + i * 16) * 36 + lc * 4] = tf32x4(wbuf[i]);
        }
        __syncthreads();
        if (kt + 1 < ntiles) {
            int ko = (kt + 1) * 8;
            if (AMODE == 1) wv4 = ((const float4*)(wvec + (kt + 1) * 32))[lc];
            #pragma unroll
            for (int i = 0; i < 4; i++) {
                abuf[i] = Ag[i * rstep + ko];
                if (AMODE == 1) {
                    abuf[i].x *= wv4.x * rv[i]; abuf[i].y *= wv4.y * rv[i];
                    abuf[i].z *= wv4.z * rv[i]; abuf[i].w *= wv4.w * rv[i];
                } else if (AMODE == 2) {
                    float4 x2 = A2g[i * rstep + ko], x3 = A3g[i * rstep + ko];
                    abuf[i].x = (abuf[i].x + x2.x) * x3.x;
                    abuf[i].y = (abuf[i].y + x2.y) * x3.y;
                    abuf[i].z = (abuf[i].z + x2.z) * x3.z;
                    abuf[i].w = (abuf[i].w + x2.w) * x3.w;
                }
                wbuf[i] = Wg[i * rstep + ko];
            }
        }
        #pragma unroll
        for (int k8 = 0; k8 < 4; k8++) {
            const int kb = k8 * 8;
            uint32_t afr[2][4], bfr[4][2];
            #pragma unroll
            for (int mi = 0; mi < 2; mi++) {
                int r = wm * 32 + mi * 16 + g;
                afr[mi][0] = __float_as_uint(As[r * 36 + kb + tig]);
                afr[mi][1] = __float_as_uint(As[(r + 8) * 36 + kb + tig]);
                afr[mi][2] = __float_as_uint(As[r * 36 + kb + tig + 4]);
                afr[mi][3] = __float_as_uint(As[(r + 8) * 36 + kb + tig + 4]);
            }
            #pragma unroll
            for (int ni = 0; ni < 4; ni++) {
                int n = wn * 32 + ni * 8 + g;
                bfr[ni][0] = __float_as_uint(Bs[n * 36 + kb + tig]);
                bfr[ni][1] = __float_as_uint(Bs[n * 36 + kb + tig + 4]);
            }
            #pragma unroll
            for (int mi = 0; mi < 2; mi++)
                #pragma unroll
                for (int ni = 0; ni < 4; ni++)
                    mma_tf32(c[mi][ni], afr[mi][0], afr[mi][1], afr[mi][2],
                             afr[mi][3], bfr[ni][0], bfr[ni][1]);
        }
    }

    #pragma unroll
    for (int mi = 0; mi < 2; mi++) {
        int r = row0 + wm * 32 + mi * 16 + g;
        #pragma unroll
        for (int ni = 0; ni < 4; ni++) {
            int n = col0 + wn * 32 + ni * 8 + 2 * tig;
            float b0 = bias[n], b1 = bias[n + 1];
            float v0 = c[mi][ni][0] + b0, v1 = c[mi][ni][1] + b1;
            float v2 = c[mi][ni][2] + b0, v3 = c[mi][ni][3] + b1;
            if (ACT == 1) { v0 = silu_f(v0); v1 = silu_f(v1); v2 = silu_f(v2); v3 = silu_f(v3); }
            else if (ACT == 2) { v0 = softplus_f(v0); v1 = softplus_f(v1); v2 = softplus_f(v2); v3 = softplus_f(v3); }
            *(float2*)&C[(size_t)r * N + n] = make_float2(v0, v1);
            *(float2*)&C[(size_t)(r + 8) * N + n] = make_float2(v2, v3);
        }
    }
}

// ---------------- mega1: inp GEMM (0..127) + res GEMM (128..191) -------------
__global__ __launch_bounds__(128) void mega1_kernel(
    const float* __restrict__ x, const float* __restrict__ mouth,
    const float* __restrict__ norm_w,
    const float* __restrict__ inp_W, const float* __restrict__ inp_b,
    const float* __restrict__ Dlin_W, const float* __restrict__ Dlin_b)
{
    __shared__ float sm[2 * 64 * 36];
    const int bid = blockIdx.x;
    if (bid < 128) {
        // P = XN @ inp_W^T + inp_b  [1024 x 512], XN folded via rowscale
        int by = bid >> 3, bx = bid & 7;
        int row0 = by * 64, col0 = bx * 64;
        const float* A_t = (row0 < HROWS) ? x + (size_t)row0 * Dm
                                          : mouth + (size_t)(row0 - HROWS) * Dm;
        gemm_core<0, 1>(sm, A_t, inp_W, inp_b, g_P, D2, Dm, row0, col0,
                        g_RMS, norm_w, nullptr, nullptr);
    } else {
        // RES = silu(XN_x @ Dlin^T + b)  [512 x 512]
        int b2 = bid - 128;
        int by = b2 >> 3, bx = b2 & 7;
        int row0 = by * 64, col0 = bx * 64;
        gemm_core<1, 1>(sm, x + (size_t)row0 * Dm, Dlin_W, Dlin_b, g_RES,
                        D2, Dm, row0, col0, g_RMS, norm_w, nullptr, nullptr);
    }
}

// ---------------- conv 3x3 SAME + silu, h-tile = 4 ---------------------------
__global__ __launch_bounds__(256) void conv_silu_kernel(
    const float* __restrict__ cw, const float* __restrict__ cb)
{
    const int bid = blockIdx.x;          // 0..127
    const int T = bid >> 6;              // 0..1 (x / mouth)
    const int h0 = (bid & 63) * 4;       // output rows h0..h0+3
    __shared__ float rows[2][6][520];
    __shared__ float wsh[36];
    __shared__ float bsh[2];
    const int t = threadIdx.x;
    if (t < 36) wsh[t] = cw[t];          // [o][i][kh][kw]
    if (t < 2) bsh[t] = cb[t];
    const float* Pb = g_P + (size_t)T * HROWS * D2;

    // load 2 channels x 6 rows (h0-1 .. h0+4), zero-padded
    for (int idx = t; idx < 2 * 6 * 128; idx += 256) {
        int i = idx / 768;
        int rem = idx - i * 768;
        int r = rem >> 7;                // 0..5
        int c4 = rem & 127;
        int hh = h0 + r - 1;
        float4 v = make_float4(0.f, 0.f, 0.f, 0.f);
        if (hh >= 0 && hh < Lh)
            v = ((const float4*)(Pb + (size_t)(i * Lh + hh) * D2))[c4];
        *(float4*)&rows[i][r][c4 * 4] = v;
    }
    __syncthreads();

    #pragma unroll
    for (int oh = 0; oh < 4; oh++) {
        #pragma unroll
        for (int ws = 0; ws < 2; ws++) {
            int w = t + ws * 256;
            float acc0 = bsh[0], acc1 = bsh[1];
            #pragma unroll
            for (int i = 0; i < 2; i++)
                #pragma unroll
                for (int kh = 0; kh < 3; kh++) {
                    float dl = (w == 0)      ? 0.f : rows[i][oh + kh][w - 1];
                    float dc = rows[i][oh + kh][w];
                    float dr = (w == D2 - 1) ? 0.f : rows[i][oh + kh][w + 1];
                    acc0 += dl * wsh[i * 9 + kh * 3 + 0]
                          + dc * wsh[i * 9 + kh * 3 + 1]
                          + dr * wsh[i * 9 + kh * 3 + 2];
                    acc1 += dl * wsh[18 + i * 9 + kh * 3 + 0]
                          + dc * wsh[18 + i * 9 + kh * 3 + 1]
                          + dr * wsh[18 + i * 9 + kh * 3 + 2];
                }
            int h = h0 + oh;
            g_XC[((size_t)T * HROWS + 0 * Lh + h) * D2 + w] = silu_f(acc0);
            g_XC[((size_t)T * HROWS + 1 * Lh + h) * D2 + w] = silu_f(acc1);
        }
    }
}

// ---------------- mega2: delta GEMM (0..127) + Bm GEMM (128..159) ------------
__global__ __launch_bounds__(128) void mega2_kernel(
    const float* __restrict__ fc1_W, const float* __restrict__ fc1_b,
    const float* __restrict__ fc2_W, const float* __restrict__ fc2_b)
{
    __shared__ float sm[2 * 64 * 36];
    const int bid = blockIdx.x;
    if (bid < 128) {
        // DELTA = softplus(XC @ fc1^T + b)  [1024 x 512]
        int by = bid >> 3, bx = bid & 7;
        int row0 = by * 64, col0 = bx * 64;
        gemm_core<2, 0>(sm, g_XC + (size_t)row0 * D2, fc1_W, fc1_b, g_DELTA,
                        D2, D2, row0, col0, nullptr, nullptr, nullptr, nullptr);
    } else {
        // BM = XC @ fc2^T + b  [1024 x 128]
        int b2 = bid - 128;               // 0..31
        int by = b2 >> 1, bx = b2 & 1;
        int row0 = by * 64, col0 = bx * 64;
        gemm_core<0, 0>(sm, g_XC + (size_t)row0 * D2, fc2_W, fc2_b, g_BM,
                        Sn, D2, row0, col0, nullptr, nullptr, nullptr, nullptr);
    }
}

// ---------------- SSM: 4-slab tf32 GEMM + S2 + Horner + silu -----------------
__global__ __launch_bounds__(128) void ssm_tf32_kernel()
{
    __shared__ float As[64 * 36];
    __shared__ float Es[4][64 * 36];
    __shared__ float s2s[64];
    const int t = threadIdx.x;
    const int lane = t & 31, warp = t >> 5;
    const int wm = warp >> 1, wn = warp & 1;
    const int g = lane >> 2, tig = lane & 3;
    const int row0 = blockIdx.y * 64, col0 = blockIdx.x * 64;
    const int lr = t >> 3, lc = t & 7;

    if (t < 64) s2s[t] = 0.f;
    float s2p = 0.f;
    {
        const float4* bm4 = (const float4*)(g_BM + (size_t)(row0 + (t >> 1)) * Sn
                                            + (t & 1) * 64);
        #pragma unroll
        for (int i = 0; i < 16; i++) {
            float4 v = bm4[i];
            s2p += v.x * v.x + v.y * v.y + v.z * v.z + v.w * v.w;
        }
    }
    __syncthreads();
    atomicAdd(&s2s[t >> 1], s2p);

    float c[4][2][4][4];
    #pragma unroll
    for (int j = 0; j < 4; j++)
        #pragma unroll
        for (int mi = 0; mi < 2; mi++)
            #pragma unroll
            for (int ni = 0; ni < 4; ni++)
                #pragma unroll
                for (int q = 0; q < 4; q++) c[j][mi][ni][q] = 0.f;

    for (int kt = 0; kt < 4; kt++) {
        __syncthreads();
        #pragma unroll
        for (int i = 0; i < 4; i++) {
            float4 v = *(const float4*)(g_BM + (size_t)(row0 + lr + i * 16) * Sn
                                        + kt * 32 + lc * 4);
            *(float4*)&As[(lr + i * 16) * 36 + lc * 4] = tf32x4(v);
        }
        #pragma unroll
        for (int j = 0; j < 4; j++)
            #pragma unroll
            for (int i = 0; i < 4; i++) {
                float4 v = *(const float4*)(g_E + (size_t)(j * D2 + col0 + lr + i * 16) * Sn
                                            + kt * 32 + lc * 4);
                *(float4*)&Es[j][(lr + i * 16) * 36 + lc * 4] = tf32x4(v);
            }
        __syncthreads();
        #pragma unroll
        for (int k8 = 0; k8 < 4; k8++) {
            const int kb = k8 * 8;
            uint32_t afr[2][4];
            #pragma unroll
            for (int mi = 0; mi < 2; mi++) {
                int r = wm * 32 + mi * 16 + g;
                afr[mi][0] = __float_as_uint(As[r * 36 + kb + tig]);
                afr[mi][1] = __float_as_uint(As[(r + 8) * 36 + kb + tig]);
                afr[mi][2] = __float_as_uint(As[r * 36 + kb + tig + 4]);
                afr[mi][3] = __float_as_uint(As[(r + 8) * 36 + kb + tig + 4]);
            }
            #pragma unroll
            for (int j = 0; j < 4; j++) {
                uint32_t bfr[4][2];
                #pragma unroll
                for (int ni = 0; ni < 4; ni++) {
                    int n = wn * 32 + ni * 8 + g;
                    bfr[ni][0] = __float_as_uint(Es[j][n * 36 + kb + tig]);
                    bfr[ni][1] = __float_as_uint(Es[j][n * 36 + kb + tig + 4]);
                }
                #pragma unroll
                for (int mi = 0; mi < 2; mi++)
                    #pragma unroll
                    for (int ni = 0; ni < 4; ni++)
                        mma_tf32(c[j][mi][ni], afr[mi][0], afr[mi][1], afr[mi][2],
                                 afr[mi][3], bfr[ni][0], bfr[ni][1]);
            }
        }
    }
    __syncthreads();

    #pragma unroll
    for (int mi = 0; mi < 2; mi++) {
        #pragma unroll
        for (int half = 0; half < 2; half++) {
            int rl = wm * 32 + mi * 16 + g + half * 8;
            int r = row0 + rl;
            float s2 = s2s[rl];
            #pragma unroll
            for (int ni = 0; ni < 4; ni++) {
                int d = col0 + wn * 32 + ni * 8 + 2 * tig;
                float2 dl = *(const float2*)&g_DELTA[(size_t)r * D2 + d];
                float2 xc = *(const float2*)&g_XC[(size_t)r * D2 + d];
                int q0 = half * 2;
                float u0 = dl.x - LN2F, u1 = dl.y - LN2F;
                float s0 = c[0][mi][ni][q0]
                         + u0 * (c[1][mi][ni][q0] + u0 * (c[2][mi][ni][q0] + u0 * c[3][mi][ni][q0]));
                float s1 = c[0][mi][ni][q0 + 1]
                         + u1 * (c[1][mi][ni][q0 + 1] + u1 * (c[2][mi][ni][q0 + 1] + u1 * c[3][mi][ni][q0 + 1]));
                s0 += xc.x * dl.x * s2;
                s1 += xc.y * dl.y * s2;
                *(float2*)&g_XS[(size_t)r * D2 + d] = make_float2(silu_f(s0), silu_f(s1));
            }
        }
    }
}

// ---------------- out GEMM with fused comb -----------------------------------
__global__ __launch_bounds__(128) void out_kernel(
    const float* __restrict__ out_W, const float* __restrict__ out_b,
    float* __restrict__ out)
{
    __shared__ float sm[2 * 64 * 36];
    const int row0 = blockIdx.y * 64, col0 = blockIdx.x * 64;
    gemm_core<0, 2>(sm, g_XS + (size_t)row0 * D2, out_W, out_b, out,
                    Dm, D2, row0, col0, nullptr, nullptr,
                    g_XS + (size_t)(HROWS + row0) * D2,
                    g_RES + (size_t)row0 * D2);
}

// ---------------- launch ----------------
extern "C" void kernel_launch(void* const* d_in, const int* in_sizes, int n_in,
                              void* d_out, int out_size)
{
    const float* x      = (const float*)d_in[0];
    const float* mouth  = (const float*)d_in[1];
    const float* norm_w = (const float*)d_in[2];
    const float* inp_W  = (const float*)d_in[3];
    const float* inp_b  = (const float*)d_in[4];
    const float* out_W  = (const float*)d_in[5];
    const float* out_b  = (const float*)d_in[6];
    const float* Dlin_W = (const float*)d_in[7];
    const float* Dlin_b = (const float*)d_in[8];
    const float* conv_W = (const float*)d_in[9];
    const float* conv_b = (const float*)d_in[10];
    const float* fc1_W  = (const float*)d_in[11];
    const float* fc1_b  = (const float*)d_in[12];
    const float* fc2_W  = (const float*)d_in[13];
    const float* fc2_b  = (const float*)d_in[14];
    const float* A      = (const float*)d_in[15];

    // 1) per-row 1/rms + E slabs
    prep_kernel<<<384, 256>>>(x, mouth, A);
    // 2) inp GEMM + res GEMM (rmsnorm folded into A-load)
    mega1_kernel<<<192, 128>>>(x, mouth, norm_w, inp_W, inp_b, Dlin_W, Dlin_b);
    // 3) conv + silu -> XC
    conv_silu_kernel<<<128, 256>>>(conv_W, conv_b);
    // 4) delta GEMM + Bm GEMM
    mega2_kernel<<<160, 128>>>(fc1_W, fc1_b, fc2_W, fc2_b);
    // 5) ssm: 4-slab GEMM + S2 + Horner + silu -> XS
    ssm_tf32_kernel<<<dim3(D2 / 64, NROWS / 64), 128>>>();
    // 6) out = ((XS_x + XS_m) * RES) @ out_W^T + out_b
    out_kernel<<<dim3(Dm / 64, HROWS / 64), 128>>>(out_W, out_b, (float*)d_out);
}

// round 8
// speedup vs baseline: 2.4356x; 1.1873x over previous
#include <cuda_runtime.h>
#include <math.h>
#include <stdint.h>

// Problem constants
#define Dm     256
#define D2     512
#define Sn     128
#define Lh     256
#define NROWS  1024   // (x rows 0..511) + (mouth rows 512..1023)
#define HROWS  512
#define LN2F   0.69314718055994531f

// ---------------- scratch (static __device__, no allocations) ----------------
__device__ float g_RMS[NROWS];         // 1/sqrt(sum x^2 + eps) per row
__device__ float g_P[NROWS * D2];      // inp projection
__device__ float g_XC[NROWS * D2];     // silu(conv(P))
__device__ float g_DELTA[NROWS * D2];  // softplus(fc1)
__device__ float g_BM[NROWS * Sn];     // fc2
__device__ float g_E[4 * D2 * Sn];     // E_j[d][n] = A^j * 2^A / j!  (d-major)
__device__ float g_XS[NROWS * D2];     // silu(ssm)
__device__ float g_RES[HROWS * D2];    // silu(Dlin(x_n))

__device__ __forceinline__ float silu_f(float v) { return v / (1.f + expf(-v)); }
__device__ __forceinline__ float softplus_f(float v) {
    return fmaxf(v, 0.f) + log1pf(expf(-fabsf(v)));
}
__device__ __forceinline__ uint32_t f2tf32(float x) {
    uint32_t r;
    asm("cvt.rna.tf32.f32 %0, %1;" : "=r"(r) : "f"(x));
    return r;
}
__device__ __forceinline__ float4 tf32x4(float4 v) {
    v.x = __uint_as_float(f2tf32(v.x));
    v.y = __uint_as_float(f2tf32(v.y));
    v.z = __uint_as_float(f2tf32(v.z));
    v.w = __uint_as_float(f2tf32(v.w));
    return v;
}
__device__ __forceinline__ void mma_tf32(float c[4],
    uint32_t a0, uint32_t a1, uint32_t a2, uint32_t a3,
    uint32_t b0, uint32_t b1)
{
    asm("mma.sync.aligned.m16n8k8.row.col.f32.tf32.tf32.f32 "
        "{%0,%1,%2,%3}, {%4,%5,%6,%7}, {%8,%9}, {%0,%1,%2,%3};"
        : "+f"(c[0]), "+f"(c[1]), "+f"(c[2]), "+f"(c[3])
        : "r"(a0), "r"(a1), "r"(a2), "r"(a3), "r"(b0), "r"(b1));
}

// ---------------- prep: per-row 1/rms (blocks 0..127) + E slabs (128..383) ----
__global__ __launch_bounds__(256) void prep_kernel(
    const float* __restrict__ x, const float* __restrict__ mouth,
    const float* __restrict__ A)
{
    const int bid = blockIdx.x, t = threadIdx.x;
    if (bid < 128) {
        int warp = t >> 5, lane = t & 31;
        int r = bid * 8 + warp;
        const float* src = (r < HROWS) ? (x + (size_t)r * Dm)
                                       : (mouth + (size_t)(r - HROWS) * Dm);
        float4 v0 = ((const float4*)src)[lane * 2];
        float4 v1 = ((const float4*)src)[lane * 2 + 1];
        float s = v0.x * v0.x + v0.y * v0.y + v0.z * v0.z + v0.w * v0.w
                + v1.x * v1.x + v1.y * v1.y + v1.z * v1.z + v1.w * v1.w;
        #pragma unroll
        for (int o = 16; o; o >>= 1) s += __shfl_xor_sync(0xffffffffu, s, o);
        if (lane == 0) g_RMS[r] = 1.f / sqrtf(s + 1e-5f);
    } else {
        int idx = (bid - 128) * 256 + t;   // d*128 + n, A is [D2][Sn]
        float a = A[idx];
        float e0 = exp2f(a);               // exp(ln2 * a)
        g_E[0 * D2 * Sn + idx] = e0;
        g_E[1 * D2 * Sn + idx] = a * e0;
        g_E[2 * D2 * Sn + idx] = 0.5f * a * a * e0;
        g_E[3 * D2 * Sn + idx] = (1.f / 6.f) * a * a * a * e0;
    }
}

// ---------------- tf32 GEMM core, 8 warps: C = A[64 x K] @ W[NxK]^T + bias ---
// 64x64 block tile, BK=32, 8 warps in 2(M) x 4(N) grid, each warp 32x16.
// AMODE 0: plain; 1: a * wvec[col] * rinv[row]; 2: (a + a2)*a3 (comb).
// ACT 0 none, 1 silu, 2 softplus. 256 threads.
template<int ACT, int AMODE>
__device__ __forceinline__ void gemm_core(
    float* sm,
    const float* __restrict__ A_t, const float* __restrict__ W,
    const float* __restrict__ bias, float* __restrict__ C,
    int N, int K, int row0, int col0,
    const float* __restrict__ rinv, const float* __restrict__ wvec,
    const float* __restrict__ A2_t, const float* __restrict__ A3_t)
{
    float* As = sm;
    float* Bs = sm + 64 * 36;
    const int t = threadIdx.x;
    const int lane = t & 31, warp = t >> 5;
    const int wm = warp & 1, wn = warp >> 1;        // 2x4 warp grid
    const int g = lane >> 2, tig = lane & 3;
    const int lr = t >> 3;        // 0..31
    const int lc = t & 7;         // float4 col within BK=32

    const float4* Ag = (const float4*)(A_t + (size_t)lr * K) + lc;
    const float4* Wg = (const float4*)(W + (size_t)(col0 + lr) * K) + lc;
    const float4* A2g = (AMODE == 2) ? (const float4*)(A2_t + (size_t)lr * K) + lc : (const float4*)0;
    const float4* A3g = (AMODE == 2) ? (const float4*)(A3_t + (size_t)lr * K) + lc : (const float4*)0;
    const size_t rstep = (size_t)8 * K;  // 32 rows in float4 units

    float rv[2];
    if (AMODE == 1) {
        rv[0] = rinv[row0 + lr];
        rv[1] = rinv[row0 + lr + 32];
    }

    float c[2][2][4];
    #pragma unroll
    for (int i = 0; i < 2; i++)
        #pragma unroll
        for (int j = 0; j < 2; j++)
            #pragma unroll
            for (int q = 0; q < 4; q++) c[i][j][q] = 0.f;

    const int ntiles = K >> 5;
    float4 abuf[2], wbuf[2];
    float4 wv4;
    if (AMODE == 1) wv4 = ((const float4*)wvec)[lc];
    #pragma unroll
    for (int i = 0; i < 2; i++) {
        abuf[i] = Ag[i * rstep];
        if (AMODE == 1) {
            abuf[i].x *= wv4.x * rv[i]; abuf[i].y *= wv4.y * rv[i];
            abuf[i].z *= wv4.z * rv[i]; abuf[i].w *= wv4.w * rv[i];
        } else if (AMODE == 2) {
            float4 x2 = A2g[i * rstep], x3 = A3g[i * rstep];
            abuf[i].x = (abuf[i].x + x2.x) * x3.x;
            abuf[i].y = (abuf[i].y + x2.y) * x3.y;
            abuf[i].z = (abuf[i].z + x2.z) * x3.z;
            abuf[i].w = (abuf[i].w + x2.w) * x3.w;
        }
        wbuf[i] = Wg[i * rstep];
    }

    for (int kt = 0; kt < ntiles; kt++) {
        __syncthreads();
        #pragma unroll
        for (int i = 0; i < 2; i++) {
            *(float4*)&As[(lr + i * 32) * 36 + lc * 4] = tf32x4(abuf[i]);
            *(float4*)&Bs[(lr + i * 32) * 36 + lc * 4] = tf32x4(wbuf[i]);
        }
        __syncthreads();
        if (kt + 1 < ntiles) {
            int ko = (kt + 1) * 8;
            if (AMODE == 1) wv4 = ((const float4*)(wvec + (kt + 1) * 32))[lc];
            #pragma unroll
            for (int i = 0; i < 2; i++) {
                abuf[i] = Ag[i * rstep + ko];
                if (AMODE == 1) {
                    abuf[i].x *= wv4.x * rv[i]; abuf[i].y *= wv4.y * rv[i];
                    abuf[i].z *= wv4.z * rv[i]; abuf[i].w *= wv4.w * rv[i];
                } else if (AMODE == 2) {
                    float4 x2 = A2g[i * rstep + ko], x3 = A3g[i * rstep + ko];
                    abuf[i].x = (abuf[i].x + x2.x) * x3.x;
                    abuf[i].y = (abuf[i].y + x2.y) * x3.y;
                    abuf[i].z = (abuf[i].z + x2.z) * x3.z;
                    abuf[i].w = (abuf[i].w + x2.w) * x3.w;
                }
                wbuf[i] = Wg[i * rstep + ko];
            }
        }
        #pragma unroll
        for (int k8 = 0; k8 < 4; k8++) {
            const int kb = k8 * 8;
            uint32_t afr[2][4], bfr[2][2];
            #pragma unroll
            for (int mi = 0; mi < 2; mi++) {
                int r = wm * 32 + mi * 16 + g;
                afr[mi][0] = __float_as_uint(As[r * 36 + kb + tig]);
                afr[mi][1] = __float_as_uint(As[(r + 8) * 36 + kb + tig]);
                afr[mi][2] = __float_as_uint(As[r * 36 + kb + tig + 4]);
                afr[mi][3] = __float_as_uint(As[(r + 8) * 36 + kb + tig + 4]);
            }
            #pragma unroll
            for (int ni = 0; ni < 2; ni++) {
                int n = wn * 16 + ni * 8 + g;
                bfr[ni][0] = __float_as_uint(Bs[n * 36 + kb + tig]);
                bfr[ni][1] = __float_as_uint(Bs[n * 36 + kb + tig + 4]);
            }
            #pragma unroll
            for (int mi = 0; mi < 2; mi++)
                #pragma unroll
                for (int ni = 0; ni < 2; ni++)
                    mma_tf32(c[mi][ni], afr[mi][0], afr[mi][1], afr[mi][2],
                             afr[mi][3], bfr[ni][0], bfr[ni][1]);
        }
    }

    #pragma unroll
    for (int mi = 0; mi < 2; mi++) {
        int r = row0 + wm * 32 + mi * 16 + g;
        #pragma unroll
        for (int ni = 0; ni < 2; ni++) {
            int n = col0 + wn * 16 + ni * 8 + 2 * tig;
            float b0 = bias[n], b1 = bias[n + 1];
            float v0 = c[mi][ni][0] + b0, v1 = c[mi][ni][1] + b1;
            float v2 = c[mi][ni][2] + b0, v3 = c[mi][ni][3] + b1;
            if (ACT == 1) { v0 = silu_f(v0); v1 = silu_f(v1); v2 = silu_f(v2); v3 = silu_f(v3); }
            else if (ACT == 2) { v0 = softplus_f(v0); v1 = softplus_f(v1); v2 = softplus_f(v2); v3 = softplus_f(v3); }
            *(float2*)&C[(size_t)r * N + n] = make_float2(v0, v1);
            *(float2*)&C[(size_t)(r + 8) * N + n] = make_float2(v2, v3);
        }
    }
}

// ---------------- mega1: inp GEMM (0..127) + res GEMM (128..191) -------------
__global__ __launch_bounds__(256) void mega1_kernel(
    const float* __restrict__ x, const float* __restrict__ mouth,
    const float* __restrict__ norm_w,
    const float* __restrict__ inp_W, const float* __restrict__ inp_b,
    const float* __restrict__ Dlin_W, const float* __restrict__ Dlin_b)
{
    __shared__ float sm[2 * 64 * 36];
    const int bid = blockIdx.x;
    if (bid < 128) {
        int by = bid >> 3, bx = bid & 7;
        int row0 = by * 64, col0 = bx * 64;
        const float* A_t = (row0 < HROWS) ? x + (size_t)row0 * Dm
                                          : mouth + (size_t)(row0 - HROWS) * Dm;
        gemm_core<0, 1>(sm, A_t, inp_W, inp_b, g_P, D2, Dm, row0, col0,
                        g_RMS, norm_w, nullptr, nullptr);
    } else {
        int b2 = bid - 128;
        int by = b2 >> 3, bx = b2 & 7;
        int row0 = by * 64, col0 = bx * 64;
        gemm_core<1, 1>(sm, x + (size_t)row0 * Dm, Dlin_W, Dlin_b, g_RES,
                        D2, Dm, row0, col0, g_RMS, norm_w, nullptr, nullptr);
    }
}

// ---------------- conv 3x3 SAME + silu, h-tile = 4 ---------------------------
__global__ __launch_bounds__(256) void conv_silu_kernel(
    const float* __restrict__ cw, const float* __restrict__ cb)
{
    const int bid = blockIdx.x;          // 0..127
    const int T = bid >> 6;              // 0..1 (x / mouth)
    const int h0 = (bid & 63) * 4;       // output rows h0..h0+3
    __shared__ float rows[2][6][520];
    __shared__ float wsh[36];
    __shared__ float bsh[2];
    const int t = threadIdx.x;
    if (t < 36) wsh[t] = cw[t];          // [o][i][kh][kw]
    if (t < 2) bsh[t] = cb[t];
    const float* Pb = g_P + (size_t)T * HROWS * D2;

    for (int idx = t; idx < 2 * 6 * 128; idx += 256) {
        int i = idx / 768;
        int rem = idx - i * 768;
        int r = rem >> 7;                // 0..5
        int c4 = rem & 127;
        int hh = h0 + r - 1;
        float4 v = make_float4(0.f, 0.f, 0.f, 0.f);
        if (hh >= 0 && hh < Lh)
            v = ((const float4*)(Pb + (size_t)(i * Lh + hh) * D2))[c4];
        *(float4*)&rows[i][r][c4 * 4] = v;
    }
    __syncthreads();

    #pragma unroll
    for (int oh = 0; oh < 4; oh++) {
        #pragma unroll
        for (int ws = 0; ws < 2; ws++) {
            int w = t + ws * 256;
            float acc0 = bsh[0], acc1 = bsh[1];
            #pragma unroll
            for (int i = 0; i < 2; i++)
                #pragma unroll
                for (int kh = 0; kh < 3; kh++) {
                    float dl = (w == 0)      ? 0.f : rows[i][oh + kh][w - 1];
                    float dc = rows[i][oh + kh][w];
                    float dr = (w == D2 - 1) ? 0.f : rows[i][oh + kh][w + 1];
                    acc0 += dl * wsh[i * 9 + kh * 3 + 0]
                          + dc * wsh[i * 9 + kh * 3 + 1]
                          + dr * wsh[i * 9 + kh * 3 + 2];
                    acc1 += dl * wsh[18 + i * 9 + kh * 3 + 0]
                          + dc * wsh[18 + i * 9 + kh * 3 + 1]
                          + dr * wsh[18 + i * 9 + kh * 3 + 2];
                }
            int h = h0 + oh;
            g_XC[((size_t)T * HROWS + 0 * Lh + h) * D2 + w] = silu_f(acc0);
            g_XC[((size_t)T * HROWS + 1 * Lh + h) * D2 + w] = silu_f(acc1);
        }
    }
}

// ---------------- mega2: delta GEMM (0..127) + Bm GEMM (128..159) ------------
__global__ __launch_bounds__(256) void mega2_kernel(
    const float* __restrict__ fc1_W, const float* __restrict__ fc1_b,
    const float* __restrict__ fc2_W, const float* __restrict__ fc2_b)
{
    __shared__ float sm[2 * 64 * 36];
    const int bid = blockIdx.x;
    if (bid < 128) {
        int by = bid >> 3, bx = bid & 7;
        int row0 = by * 64, col0 = bx * 64;
        gemm_core<2, 0>(sm, g_XC + (size_t)row0 * D2, fc1_W, fc1_b, g_DELTA,
                        D2, D2, row0, col0, nullptr, nullptr, nullptr, nullptr);
    } else {
        int b2 = bid - 128;               // 0..31
        int by = b2 >> 1, bx = b2 & 1;
        int row0 = by * 64, col0 = bx * 64;
        gemm_core<0, 0>(sm, g_XC + (size_t)row0 * D2, fc2_W, fc2_b, g_BM,
                        Sn, D2, row0, col0, nullptr, nullptr, nullptr, nullptr);
    }
}

// ---------------- SSM: 4-slab tf32 GEMM + S2 + Horner + silu, 8 warps --------
__global__ __launch_bounds__(256) void ssm_tf32_kernel()
{
    __shared__ float As[64 * 36];
    __shared__ float Es[4][64 * 36];
    __shared__ float s2s[64];
    const int t = threadIdx.x;
    const int lane = t & 31, warp = t >> 5;
    const int wm = warp & 1, wn = warp >> 1;        // 2x4 warp grid
    const int g = lane >> 2, tig = lane & 3;
    const int row0 = blockIdx.y * 64, col0 = blockIdx.x * 64;
    const int lr = t >> 3, lc = t & 7;

    if (t < 64) s2s[t] = 0.f;
    // per-row sum of Bm^2: 4 threads per row, 32 elems each
    float s2p = 0.f;
    {
        const float4* bm4 = (const float4*)(g_BM + (size_t)(row0 + (t >> 2)) * Sn
                                            + (t & 3) * 32);
        #pragma unroll
        for (int i = 0; i < 8; i++) {
            float4 v = bm4[i];
            s2p += v.x * v.x + v.y * v.y + v.z * v.z + v.w * v.w;
        }
    }
    __syncthreads();
    atomicAdd(&s2s[t >> 2], s2p);

    float c[4][2][2][4];
    #pragma unroll
    for (int j = 0; j < 4; j++)
        #pragma unroll
        for (int mi = 0; mi < 2; mi++)
            #pragma unroll
            for (int ni = 0; ni < 2; ni++)
                #pragma unroll
                for (int q = 0; q < 4; q++) c[j][mi][ni][q] = 0.f;

    for (int kt = 0; kt < 4; kt++) {
        __syncthreads();
        #pragma unroll
        for (int i = 0; i < 2; i++) {
            float4 v = *(const float4*)(g_BM + (size_t)(row0 + lr + i * 32) * Sn
                                        + kt * 32 + lc * 4);
            *(float4*)&As[(lr + i * 32) * 36 + lc * 4] = tf32x4(v);
        }
        #pragma unroll
        for (int j = 0; j < 4; j++)
            #pragma unroll
            for (int i = 0; i < 2; i++) {
                float4 v = *(const float4*)(g_E + (size_t)(j * D2 + col0 + lr + i * 32) * Sn
                                            + kt * 32 + lc * 4);
                *(float4*)&Es[j][(lr + i * 32) * 36 + lc * 4] = tf32x4(v);
            }
        __syncthreads();
        #pragma unroll
        for (int k8 = 0; k8 < 4; k8++) {
            const int kb = k8 * 8;
            uint32_t afr[2][4];
            #pragma unroll
            for (int mi = 0; mi < 2; mi++) {
                int r = wm * 32 + mi * 16 + g;
                afr[mi][0] = __float_as_uint(As[r * 36 + kb + tig]);
                afr[mi][1] = __float_as_uint(As[(r + 8) * 36 + kb + tig]);
                afr[mi][2] = __float_as_uint(As[r * 36 + kb + tig + 4]);
                afr[mi][3] = __float_as_uint(As[(r + 8) * 36 + kb + tig + 4]);
            }
            #pragma unroll
            for (int j = 0; j < 4; j++) {
                uint32_t bfr[2][2];
                #pragma unroll
                for (int ni = 0; ni < 2; ni++) {
                    int n = wn * 16 + ni * 8 + g;
                    bfr[ni][0] = __float_as_uint(Es[j][n * 36 + kb + tig]);
                    bfr[ni][1] = __float_as_uint(Es[j][n * 36 + kb + tig + 4]);
                }
                #pragma unroll
                for (int mi = 0; mi < 2; mi++)
                    #pragma unroll
                    for (int ni = 0; ni < 2; ni++)
                        mma_tf32(c[j][mi][ni], afr[mi][0], afr[mi][1], afr[mi][2],
                                 afr[mi][3], bfr[ni][0], bfr[ni][1]);
            }
        }
    }
    __syncthreads();

    #pragma unroll
    for (int mi = 0; mi < 2; mi++) {
        #pragma unroll
        for (int half = 0; half < 2; half++) {
            int rl = wm * 32 + mi * 16 + g + half * 8;
            int r = row0 + rl;
            float s2 = s2s[rl];
            #pragma unroll
            for (int ni = 0; ni < 2; ni++) {
                int d = col0 + wn * 16 + ni * 8 + 2 * tig;
                float2 dl = *(const float2*)&g_DELTA[(size_t)r * D2 + d];
                float2 xc = *(const float2*)&g_XC[(size_t)r * D2 + d];
                int q0 = half * 2;
                float u0 = dl.x - LN2F, u1 = dl.y - LN2F;
                float s0 = c[0][mi][ni][q0]
                         + u0 * (c[1][mi][ni][q0] + u0 * (c[2][mi][ni][q0] + u0 * c[3][mi][ni][q0]));
                float s1 = c[0][mi][ni][q0 + 1]
                         + u1 * (c[1][mi][ni][q0 + 1] + u1 * (c[2][mi][ni][q0 + 1] + u1 * c[3][mi][ni][q0 + 1]));
                s0 += xc.x * dl.x * s2;
                s1 += xc.y * dl.y * s2;
                *(float2*)&g_XS[(size_t)r * D2 + d] = make_float2(silu_f(s0), silu_f(s1));
            }
        }
    }
}

// ---------------- out GEMM with fused comb -----------------------------------
__global__ __launch_bounds__(256) void out_kernel(
    const float* __restrict__ out_W, const float* __restrict__ out_b,
    float* __restrict__ out)
{
    __shared__ float sm[2 * 64 * 36];
    const int row0 = blockIdx.y * 64, col0 = blockIdx.x * 64;
    gemm_core<0, 2>(sm, g_XS + (size_t)row0 * D2, out_W, out_b, out,
                    Dm, D2, row0, col0, nullptr, nullptr,
                    g_XS + (size_t)(HROWS + row0) * D2,
                    g_RES + (size_t)row0 * D2);
}

// ---------------- launch ----------------
extern "C" void kernel_launch(void* const* d_in, const int* in_sizes, int n_in,
                              void* d_out, int out_size)
{
    const float* x      = (const float*)d_in[0];
    const float* mouth  = (const float*)d_in[1];
    const float* norm_w = (const float*)d_in[2];
    const float* inp_W  = (const float*)d_in[3];
    const float* inp_b  = (const float*)d_in[4];
    const float* out_W  = (const float*)d_in[5];
    const float* out_b  = (const float*)d_in[6];
    const float* Dlin_W = (const float*)d_in[7];
    const float* Dlin_b = (const float*)d_in[8];
    const float* conv_W = (const float*)d_in[9];
    const float* conv_b = (const float*)d_in[10];
    const float* fc1_W  = (const float*)d_in[11];
    const float* fc1_b  = (const float*)d_in[12];
    const float* fc2_W  = (const float*)d_in[13];
    const float* fc2_b  = (const float*)d_in[14];
    const float* A      = (const float*)d_in[15];

    // 1) per-row 1/rms + E slabs
    prep_kernel<<<384, 256>>>(x, mouth, A);
    // 2) inp GEMM + res GEMM (rmsnorm folded into A-load)
    mega1_kernel<<<192, 256>>>(x, mouth, norm_w, inp_W, inp_b, Dlin_W, Dlin_b);
    // 3) conv + silu -> XC
    conv_silu_kernel<<<128, 256>>>(conv_W, conv_b);
    // 4) delta GEMM + Bm GEMM
    mega2_kernel<<<160, 256>>>(fc1_W, fc1_b, fc2_W, fc2_b);
    // 5) ssm: 4-slab GEMM + S2 + Horner + silu -> XS
    ssm_tf32_kernel<<<dim3(D2 / 64, NROWS / 64), 256>>>();
    // 6) out = ((XS_x + XS_m) * RES) @ out_W^T + out_b
    out_kernel<<<dim3(Dm / 64, HROWS / 64), 256>>>(out_W, out_b, (float*)d_out);
}

// round 9
// speedup vs baseline: 2.5697x; 1.0551x over previous
#include <cuda_runtime.h>
#include <cuda_bf16.h>
#include <math.h>
#include <stdint.h>

// Problem constants
#define Dm     256
#define D2     512
#define Sn     128
#define Lh     256
#define NROWS  1024   // (x rows 0..511) + (mouth rows 512..1023)
#define HROWS  512
#define LN2F   0.69314718055994531f
#define SROW   20     // smem row stride in uint32 words (16 data + 4 pad)

// ---------------- scratch (static __device__, no allocations) ----------------
__device__ float g_RMS[NROWS];         // 1/sqrt(sum x^2 + eps) per row
__device__ float g_P[NROWS * D2];      // inp projection
__device__ float g_XC[NROWS * D2];     // silu(conv(P))
__device__ float g_DELTA[NROWS * D2];  // softplus(fc1)
__device__ float g_BM[NROWS * Sn];     // fc2
__device__ float g_E[4 * D2 * Sn];     // E_j[d][n] = A^j * 2^A / j!  (d-major)
__device__ float g_XS[NROWS * D2];     // silu(ssm)
__device__ float g_RES[HROWS * D2];    // silu(Dlin(x_n))

__device__ __forceinline__ float silu_f(float v) { return v / (1.f + expf(-v)); }
__device__ __forceinline__ float softplus_f(float v) {
    return fmaxf(v, 0.f) + log1pf(expf(-fabsf(v)));
}
__device__ __forceinline__ uint32_t pk(float a, float b) {
    __nv_bfloat162 h = __floats2bfloat162_rn(a, b);
    return *reinterpret_cast<uint32_t*>(&h);
}
__device__ __forceinline__ uint4 pack8(float4 u, float4 v) {
    return make_uint4(pk(u.x, u.y), pk(u.z, u.w), pk(v.x, v.y), pk(v.z, v.w));
}
__device__ __forceinline__ void mma_bf16(float c[4],
    uint32_t a0, uint32_t a1, uint32_t a2, uint32_t a3,
    uint32_t b0, uint32_t b1)
{
    asm("mma.sync.aligned.m16n8k16.row.col.f32.bf16.bf16.f32 "
        "{%0,%1,%2,%3}, {%4,%5,%6,%7}, {%8,%9}, {%0,%1,%2,%3};"
        : "+f"(c[0]), "+f"(c[1]), "+f"(c[2]), "+f"(c[3])
        : "r"(a0), "r"(a1), "r"(a2), "r"(a3), "r"(b0), "r"(b1));
}

// ---------------- prep: per-row 1/rms (blocks 0..127) + E slabs (128..383) ----
__global__ __launch_bounds__(256) void prep_kernel(
    const float* __restrict__ x, const float* __restrict__ mouth,
    const float* __restrict__ A)
{
    const int bid = blockIdx.x, t = threadIdx.x;
    if (bid < 128) {
        int warp = t >> 5, lane = t & 31;
        int r = bid * 8 + warp;
        const float* src = (r < HROWS) ? (x + (size_t)r * Dm)
                                       : (mouth + (size_t)(r - HROWS) * Dm);
        float4 v0 = ((const float4*)src)[lane * 2];
        float4 v1 = ((const float4*)src)[lane * 2 + 1];
        float s = v0.x * v0.x + v0.y * v0.y + v0.z * v0.z + v0.w * v0.w
                + v1.x * v1.x + v1.y * v1.y + v1.z * v1.z + v1.w * v1.w;
        #pragma unroll
        for (int o = 16; o; o >>= 1) s += __shfl_xor_sync(0xffffffffu, s, o);
        if (lane == 0) g_RMS[r] = 1.f / sqrtf(s + 1e-5f);
    } else {
        int idx = (bid - 128) * 256 + t;   // d*128 + n, A is [D2][Sn]
        float a = A[idx];
        float e0 = exp2f(a);               // exp(ln2 * a)
        g_E[0 * D2 * Sn + idx] = e0;
        g_E[1 * D2 * Sn + idx] = a * e0;
        g_E[2 * D2 * Sn + idx] = 0.5f * a * a * e0;
        g_E[3 * D2 * Sn + idx] = (1.f / 6.f) * a * a * a * e0;
    }
}

// ---------------- bf16 GEMM core, 8 warps: C = A[64 x K] @ W[NxK]^T + bias ---
// 64x64 block tile, BK=32, 8 warps in 2(M) x 4(N) grid (warp 32x16),
// m16n8k16 bf16 mma, fp32 accumulate. 256 threads.
// AMODE 0: plain; 1: a * wvec[col] * rinv[row]; 2: (a + a2)*a3 (comb).
// ACT 0 none, 1 silu, 2 softplus.
template<int ACT, int AMODE>
__device__ __forceinline__ void gemm_core(
    uint32_t* smbuf,
    const float* __restrict__ A_t, const float* __restrict__ W,
    const float* __restrict__ bias, float* __restrict__ C,
    int N, int K, int row0, int col0,
    const float* __restrict__ rinv, const float* __restrict__ wvec,
    const float* __restrict__ A2_t, const float* __restrict__ A3_t)
{
    uint32_t* As = smbuf;               // 64 x SROW words
    uint32_t* Bs = smbuf + 64 * SROW;   // 64 x SROW words
    const int t = threadIdx.x;
    const int lane = t & 31, warp = t >> 5;
    const int wm = warp & 1, wn = warp >> 1;        // 2x4 warp grid
    const int g = lane >> 2, tig = lane & 3;
    const int ar = t >> 2;        // 0..63 (tile row)
    const int ac = (t & 3) * 8;   // float col offset within BK=32

    const float* Ap = A_t + (size_t)ar * K + ac;
    const float* Wp = W + (size_t)(col0 + ar) * K + ac;
    const float* A2p = (AMODE == 2) ? A2_t + (size_t)ar * K + ac : (const float*)0;
    const float* A3p = (AMODE == 2) ? A3_t + (size_t)ar * K + ac : (const float*)0;
    const float rv = (AMODE == 1) ? rinv[row0 + ar] : 0.f;

    float c[2][2][4];
    #pragma unroll
    for (int i = 0; i < 2; i++)
        #pragma unroll
        for (int j = 0; j < 2; j++)
            #pragma unroll
            for (int q = 0; q < 4; q++) c[i][j][q] = 0.f;

    const int ntiles = K >> 5;
    uint4 ab, wb;

#define LOAD_AB(ko) do { \
    float4 u = *(const float4*)(Ap + (ko)); \
    float4 v = *(const float4*)(Ap + (ko) + 4); \
    if (AMODE == 1) { \
        float4 w0 = *(const float4*)(wvec + (ko) + ac); \
        float4 w1 = *(const float4*)(wvec + (ko) + ac + 4); \
        u.x *= w0.x * rv; u.y *= w0.y * rv; u.z *= w0.z * rv; u.w *= w0.w * rv; \
        v.x *= w1.x * rv; v.y *= w1.y * rv; v.z *= w1.z * rv; v.w *= w1.w * rv; \
    } else if (AMODE == 2) { \
        float4 u2 = *(const float4*)(A2p + (ko)), u3 = *(const float4*)(A3p + (ko)); \
        float4 v2 = *(const float4*)(A2p + (ko) + 4), v3 = *(const float4*)(A3p + (ko) + 4); \
        u.x = (u.x + u2.x) * u3.x; u.y = (u.y + u2.y) * u3.y; \
        u.z = (u.z + u2.z) * u3.z; u.w = (u.w + u2.w) * u3.w; \
        v.x = (v.x + v2.x) * v3.x; v.y = (v.y + v2.y) * v3.y; \
        v.z = (v.z + v2.z) * v3.z; v.w = (v.w + v2.w) * v3.w; \
    } \
    ab = pack8(u, v); \
    float4 xx = *(const float4*)(Wp + (ko)); \
    float4 yy = *(const float4*)(Wp + (ko) + 4); \
    wb = pack8(xx, yy); \
} while (0)

    LOAD_AB(0);
    for (int kt = 0; kt < ntiles; kt++) {
        __syncthreads();
        *(uint4*)&As[ar * SROW + (t & 3) * 4] = ab;
        *(uint4*)&Bs[ar * SROW + (t & 3) * 4] = wb;
        __syncthreads();
        if (kt + 1 < ntiles) LOAD_AB((kt + 1) * 32);
        #pragma unroll
        for (int k16 = 0; k16 < 2; k16++) {
            const int kb = k16 * 8;
            uint32_t afr[2][4], bfr[2][2];
            #pragma unroll
            for (int mi = 0; mi < 2; mi++) {
                int r = wm * 32 + mi * 16 + g;
                afr[mi][0] = As[r * SROW + kb + tig];
                afr[mi][1] = As[(r + 8) * SROW + kb + tig];
                afr[mi][2] = As[r * SROW + kb + tig + 4];
                afr[mi][3] = As[(r + 8) * SROW + kb + tig + 4];
            }
            #pragma unroll
            for (int ni = 0; ni < 2; ni++) {
                int n = wn * 16 + ni * 8 + g;
                bfr[ni][0] = Bs[n * SROW + kb + tig];
                bfr[ni][1] = Bs[n * SROW + kb + tig + 4];
            }
            #pragma unroll
            for (int mi = 0; mi < 2; mi++)
                #pragma unroll
                for (int ni = 0; ni < 2; ni++)
                    mma_bf16(c[mi][ni], afr[mi][0], afr[mi][1], afr[mi][2],
                             afr[mi][3], bfr[ni][0], bfr[ni][1]);
        }
    }
#undef LOAD_AB

    #pragma unroll
    for (int mi = 0; mi < 2; mi++) {
        int r = row0 + wm * 32 + mi * 16 + g;
        #pragma unroll
        for (int ni = 0; ni < 2; ni++) {
            int n = col0 + wn * 16 + ni * 8 + 2 * tig;
            float b0 = bias[n], b1 = bias[n + 1];
            float v0 = c[mi][ni][0] + b0, v1 = c[mi][ni][1] + b1;
            float v2 = c[mi][ni][2] + b0, v3 = c[mi][ni][3] + b1;
            if (ACT == 1) { v0 = silu_f(v0); v1 = silu_f(v1); v2 = silu_f(v2); v3 = silu_f(v3); }
            else if (ACT == 2) { v0 = softplus_f(v0); v1 = softplus_f(v1); v2 = softplus_f(v2); v3 = softplus_f(v3); }
            *(float2*)&C[(size_t)r * N + n] = make_float2(v0, v1);
            *(float2*)&C[(size_t)(r + 8) * N + n] = make_float2(v2, v3);
        }
    }
}

// ---------------- mega1: inp GEMM (0..127) + res GEMM (128..191) -------------
__global__ __launch_bounds__(256) void mega1_kernel(
    const float* __restrict__ x, const float* __restrict__ mouth,
    const float* __restrict__ norm_w,
    const float* __restrict__ inp_W, const float* __restrict__ inp_b,
    const float* __restrict__ Dlin_W, const float* __restrict__ Dlin_b)
{
    __shared__ uint32_t sm[2 * 64 * SROW];
    const int bid = blockIdx.x;
    if (bid < 128) {
        int by = bid >> 3, bx = bid & 7;
        int row0 = by * 64, col0 = bx * 64;
        const float* A_t = (row0 < HROWS) ? x + (size_t)row0 * Dm
                                          : mouth + (size_t)(row0 - HROWS) * Dm;
        gemm_core<0, 1>(sm, A_t, inp_W, inp_b, g_P, D2, Dm, row0, col0,
                        g_RMS, norm_w, nullptr, nullptr);
    } else {
        int b2 = bid - 128;
        int by = b2 >> 3, bx = b2 & 7;
        int row0 = by * 64, col0 = bx * 64;
        gemm_core<1, 1>(sm, x + (size_t)row0 * Dm, Dlin_W, Dlin_b, g_RES,
                        D2, Dm, row0, col0, g_RMS, norm_w, nullptr, nullptr);
    }
}

// ---------------- conv 3x3 SAME + silu, h-tile = 4 ---------------------------
__global__ __launch_bounds__(256) void conv_silu_kernel(
    const float* __restrict__ cw, const float* __restrict__ cb)
{
    const int bid = blockIdx.x;          // 0..127
    const int T = bid >> 6;              // 0..1 (x / mouth)
    const int h0 = (bid & 63) * 4;       // output rows h0..h0+3
    __shared__ float rows[2][6][520];
    __shared__ float wsh[36];
    __shared__ float bsh[2];
    const int t = threadIdx.x;
    if (t < 36) wsh[t] = cw[t];          // [o][i][kh][kw]
    if (t < 2) bsh[t] = cb[t];
    const float* Pb = g_P + (size_t)T * HROWS * D2;

    for (int idx = t; idx < 2 * 6 * 128; idx += 256) {
        int i = idx / 768;
        int rem = idx - i * 768;
        int r = rem >> 7;                // 0..5
        int c4 = rem & 127;
        int hh = h0 + r - 1;
        float4 v = make_float4(0.f, 0.f, 0.f, 0.f);
        if (hh >= 0 && hh < Lh)
            v = ((const float4*)(Pb + (size_t)(i * Lh + hh) * D2))[c4];
        *(float4*)&rows[i][r][c4 * 4] = v;
    }
    __syncthreads();

    #pragma unroll
    for (int oh = 0; oh < 4; oh++) {
        #pragma unroll
        for (int ws = 0; ws < 2; ws++) {
            int w = t + ws * 256;
            float acc0 = bsh[0], acc1 = bsh[1];
            #pragma unroll
            for (int i = 0; i < 2; i++)
                #pragma unroll
                for (int kh = 0; kh < 3; kh++) {
                    float dl = (w == 0)      ? 0.f : rows[i][oh + kh][w - 1];
                    float dc = rows[i][oh + kh][w];
                    float dr = (w == D2 - 1) ? 0.f : rows[i][oh + kh][w + 1];
                    acc0 += dl * wsh[i * 9 + kh * 3 + 0]
                          + dc * wsh[i * 9 + kh * 3 + 1]
                          + dr * wsh[i * 9 + kh * 3 + 2];
                    acc1 += dl * wsh[18 + i * 9 + kh * 3 + 0]
                          + dc * wsh[18 + i * 9 + kh * 3 + 1]
                          + dr * wsh[18 + i * 9 + kh * 3 + 2];
                }
            int h = h0 + oh;
            g_XC[((size_t)T * HROWS + 0 * Lh + h) * D2 + w] = silu_f(acc0);
            g_XC[((size_t)T * HROWS + 1 * Lh + h) * D2 + w] = silu_f(acc1);
        }
    }
}

// ---------------- mega2: delta GEMM (0..127) + Bm GEMM (128..159) ------------
__global__ __launch_bounds__(256) void mega2_kernel(
    const float* __restrict__ fc1_W, const float* __restrict__ fc1_b,
    const float* __restrict__ fc2_W, const float* __restrict__ fc2_b)
{
    __shared__ uint32_t sm[2 * 64 * SROW];
    const int bid = blockIdx.x;
    if (bid < 128) {
        int by = bid >> 3, bx = bid & 7;
        int row0 = by * 64, col0 = bx * 64;
        gemm_core<2, 0>(sm, g_XC + (size_t)row0 * D2, fc1_W, fc1_b, g_DELTA,
                        D2, D2, row0, col0, nullptr, nullptr, nullptr, nullptr);
    } else {
        int b2 = bid - 128;               // 0..31
        int by = b2 >> 1, bx = b2 & 1;
        int row0 = by * 64, col0 = bx * 64;
        gemm_core<0, 0>(sm, g_XC + (size_t)row0 * D2, fc2_W, fc2_b, g_BM,
                        Sn, D2, row0, col0, nullptr, nullptr, nullptr, nullptr);
    }
}

// ---------------- SSM: 4-slab bf16 GEMM + S2 + Horner + silu, 8 warps --------
__global__ __launch_bounds__(256) void ssm_kernel()
{
    __shared__ uint32_t As[64 * SROW];
    __shared__ uint32_t Es[4][64 * SROW];
    __shared__ float s2s[64];
    const int t = threadIdx.x;
    const int lane = t & 31, warp = t >> 5;
    const int wm = warp & 1, wn = warp >> 1;        // 2x4 warp grid
    const int g = lane >> 2, tig = lane & 3;
    const int row0 = blockIdx.y * 64, col0 = blockIdx.x * 64;
    const int ar = t >> 2, ac = (t & 3) * 8;

    if (t < 64) s2s[t] = 0.f;
    // per-row sum of Bm^2 (fp32 exact): 4 threads per row, 32 elems each
    float s2p = 0.f;
    {
        const float4* bm4 = (const float4*)(g_BM + (size_t)(row0 + (t >> 2)) * Sn
                                            + (t & 3) * 32);
        #pragma unroll
        for (int i = 0; i < 8; i++) {
            float4 v = bm4[i];
            s2p += v.x * v.x + v.y * v.y + v.z * v.z + v.w * v.w;
        }
    }
    __syncthreads();
    atomicAdd(&s2s[t >> 2], s2p);

    float c[4][2][2][4];
    #pragma unroll
    for (int j = 0; j < 4; j++)
        #pragma unroll
        for (int mi = 0; mi < 2; mi++)
            #pragma unroll
            for (int ni = 0; ni < 2; ni++)
                #pragma unroll
                for (int q = 0; q < 4; q++) c[j][mi][ni][q] = 0.f;

    for (int kt = 0; kt < 4; kt++) {
        __syncthreads();
        {
            const float* p = g_BM + (size_t)(row0 + ar) * Sn + kt * 32 + ac;
            float4 u = *(const float4*)p, v = *(const float4*)(p + 4);
            *(uint4*)&As[ar * SROW + (t & 3) * 4] = pack8(u, v);
        }
        #pragma unroll
        for (int j = 0; j < 4; j++) {
            const float* p = g_E + (size_t)(j * D2 + col0 + ar) * Sn + kt * 32 + ac;
            float4 u = *(const float4*)p, v = *(const float4*)(p + 4);
            *(uint4*)&Es[j][ar * SROW + (t & 3) * 4] = pack8(u, v);
        }
        __syncthreads();
        #pragma unroll
        for (int k16 = 0; k16 < 2; k16++) {
            const int kb = k16 * 8;
            uint32_t afr[2][4];
            #pragma unroll
            for (int mi = 0; mi < 2; mi++) {
                int r = wm * 32 + mi * 16 + g;
                afr[mi][0] = As[r * SROW + kb + tig];
                afr[mi][1] = As[(r + 8) * SROW + kb + tig];
                afr[mi][2] = As[r * SROW + kb + tig + 4];
                afr[mi][3] = As[(r + 8) * SROW + kb + tig + 4];
            }
            #pragma unroll
            for (int j = 0; j < 4; j++) {
                uint32_t bfr[2][2];
                #pragma unroll
                for (int ni = 0; ni < 2; ni++) {
                    int n = wn * 16 + ni * 8 + g;
                    bfr[ni][0] = Es[j][n * SROW + kb + tig];
                    bfr[ni][1] = Es[j][n * SROW + kb + tig + 4];
                }
                #pragma unroll
                for (int mi = 0; mi < 2; mi++)
                    #pragma unroll
                    for (int ni = 0; ni < 2; ni++)
                        mma_bf16(c[j][mi][ni], afr[mi][0], afr[mi][1], afr[mi][2],
                                 afr[mi][3], bfr[ni][0], bfr[ni][1]);
            }
        }
    }
    __syncthreads();

    #pragma unroll
    for (int mi = 0; mi < 2; mi++) {
        #pragma unroll
        for (int half = 0; half < 2; half++) {
            int rl = wm * 32 + mi * 16 + g + half * 8;
            int r = row0 + rl;
            float s2 = s2s[rl];
            #pragma unroll
            for (int ni = 0; ni < 2; ni++) {
                int d = col0 + wn * 16 + ni * 8 + 2 * tig;
                float2 dl = *(const float2*)&g_DELTA[(size_t)r * D2 + d];
                float2 xc = *(const float2*)&g_XC[(size_t)r * D2 + d];
                int q0 = half * 2;
                float u0 = dl.x - LN2F, u1 = dl.y - LN2F;
                float s0 = c[0][mi][ni][q0]
                         + u0 * (c[1][mi][ni][q0] + u0 * (c[2][mi][ni][q0] + u0 * c[3][mi][ni][q0]));
                float s1 = c[0][mi][ni][q0 + 1]
                         + u1 * (c[1][mi][ni][q0 + 1] + u1 * (c[2][mi][ni][q0 + 1] + u1 * c[3][mi][ni][q0 + 1]));
                s0 += xc.x * dl.x * s2;
                s1 += xc.y * dl.y * s2;
                *(float2*)&g_XS[(size_t)r * D2 + d] = make_float2(silu_f(s0), silu_f(s1));
            }
        }
    }
}

// ---------------- out GEMM with fused comb -----------------------------------
__global__ __launch_bounds__(256) void out_kernel(
    const float* __restrict__ out_W, const float* __restrict__ out_b,
    float* __restrict__ out)
{
    __shared__ uint32_t sm[2 * 64 * SROW];
    const int row0 = blockIdx.y * 64, col0 = blockIdx.x * 64;
    gemm_core<0, 2>(sm, g_XS + (size_t)row0 * D2, out_W, out_b, out,
                    Dm, D2, row0, col0, nullptr, nullptr,
                    g_XS + (size_t)(HROWS + row0) * D2,
                    g_RES + (size_t)row0 * D2);
}

// ---------------- launch ----------------
extern "C" void kernel_launch(void* const* d_in, const int* in_sizes, int n_in,
                              void* d_out, int out_size)
{
    const float* x      = (const float*)d_in[0];
    const float* mouth  = (const float*)d_in[1];
    const float* norm_w = (const float*)d_in[2];
    const float* inp_W  = (const float*)d_in[3];
    const float* inp_b  = (const float*)d_in[4];
    const float* out_W  = (const float*)d_in[5];
    const float* out_b  = (const float*)d_in[6];
    const float* Dlin_W = (const float*)d_in[7];
    const float* Dlin_b = (const float*)d_in[8];
    const float* conv_W = (const float*)d_in[9];
    const float* conv_b = (const float*)d_in[10];
    const float* fc1_W  = (const float*)d_in[11];
    const float* fc1_b  = (const float*)d_in[12];
    const float* fc2_W  = (const float*)d_in[13];
    const float* fc2_b  = (const float*)d_in[14];
    const float* A      = (const float*)d_in[15];

    // 1) per-row 1/rms + E slabs
    prep_kernel<<<384, 256>>>(x, mouth, A);
    // 2) inp GEMM + res GEMM (rmsnorm folded into A-load)
    mega1_kernel<<<192, 256>>>(x, mouth, norm_w, inp_W, inp_b, Dlin_W, Dlin_b);
    // 3) conv + silu -> XC
    conv_silu_kernel<<<128, 256>>>(conv_W, conv_b);
    // 4) delta GEMM + Bm GEMM
    mega2_kernel<<<160, 256>>>(fc1_W, fc1_b, fc2_W, fc2_b);
    // 5) ssm: 4-slab GEMM + S2 + Horner + silu -> XS
    ssm_kernel<<<dim3(D2 / 64, NROWS / 64), 256>>>();
    // 6) out = ((XS_x + XS_m) * RES) @ out_W^T + out_b
    out_kernel<<<dim3(Dm / 64, HROWS / 64), 256>>>(out_W, out_b, (float*)d_out);
}

// round 10
// speedup vs baseline: 3.0501x; 1.1869x over previous
#include <cuda_runtime.h>
#include <cuda_bf16.h>
#include <math.h>
#include <stdint.h>

// Problem constants
#define Dm     256
#define D2     512
#define Sn     128
#define Lh     256
#define NROWS  1024   // (x rows 0..511) + (mouth rows 512..1023)
#define HROWS  512
#define LN2F   0.69314718055994531f
#define SROW   20            // smem row stride in uint32 words (16 data + 4 pad)
#define STGW   (64 * SROW)   // words per 64x32-bf16 tile

// ---------------- scratch (static __device__, no allocations) ----------------
__device__ __nv_bfloat16 g_XNbf[NROWS * Dm];   // rmsnormed x|mouth (bf16)
__device__ __nv_bfloat16 g_Wibf[D2 * Dm];      // inp_W bf16
__device__ __nv_bfloat16 g_Wdbf[D2 * Dm];      // Dlin_W bf16
__device__ __nv_bfloat16 g_W1bf[D2 * D2];      // fc1_W bf16
__device__ __nv_bfloat16 g_W2bf[Sn * D2];      // fc2_W bf16
__device__ __nv_bfloat16 g_Pbf[NROWS * D2];    // inp projection (bf16)
__device__ __nv_bfloat16 g_XCbf[NROWS * D2];   // silu(conv(P)) (bf16)
__device__ float         g_DELTA[NROWS * D2];  // softplus(fc1) (fp32, epilogue-only)
__device__ __nv_bfloat16 g_BMbf[NROWS * Sn];   // fc2 (bf16)
__device__ __nv_bfloat16 g_Ebf[4 * D2 * Sn];   // E_j[d][n] = A^j 2^A / j! (bf16)
__device__ float         g_XS[NROWS * D2];     // silu(ssm) (fp32)
__device__ float         g_RES[HROWS * D2];    // silu(Dlin(x_n)) (fp32)

__device__ __forceinline__ float silu_f(float v) { return v / (1.f + expf(-v)); }
__device__ __forceinline__ float softplus_f(float v) {
    return fmaxf(v, 0.f) + log1pf(expf(-fabsf(v)));
}
__device__ __forceinline__ uint32_t pk(float a, float b) {
    __nv_bfloat162 h = __floats2bfloat162_rn(a, b);
    return *reinterpret_cast<uint32_t*>(&h);
}
__device__ __forceinline__ uint4 pack8(float4 u, float4 v) {
    return make_uint4(pk(u.x, u.y), pk(u.z, u.w), pk(v.x, v.y), pk(v.z, v.w));
}
__device__ __forceinline__ void mma_bf16(float c[4],
    uint32_t a0, uint32_t a1, uint32_t a2, uint32_t a3,
    uint32_t b0, uint32_t b1)
{
    asm("mma.sync.aligned.m16n8k16.row.col.f32.bf16.bf16.f32 "
        "{%0,%1,%2,%3}, {%4,%5,%6,%7}, {%8,%9}, {%0,%1,%2,%3};"
        : "+f"(c[0]), "+f"(c[1]), "+f"(c[2]), "+f"(c[3])
        : "r"(a0), "r"(a1), "r"(a2), "r"(a3), "r"(b0), "r"(b1));
}
__device__ __forceinline__ void cpa16(uint32_t saddr, const void* g) {
    asm volatile("cp.async.ca.shared.global [%0], [%1], 16;"
                 :: "r"(saddr), "l"(g) : "memory");
}
#define CP_COMMIT() asm volatile("cp.async.commit_group;" ::: "memory")
#define CP_WAIT1()  asm volatile("cp.async.wait_group 1;" ::: "memory")

// ---------------- prep: XNbf + E slabs + weight->bf16 ------------------------
// blocks [0,128): rmsnorm (8 warps, 1 row/warp) -> g_XNbf
// blocks [128,384): E slabs bf16
// blocks [384,672): weight conversion (2048 elems/block)
__global__ __launch_bounds__(256) void prep_kernel(
    const float* __restrict__ x, const float* __restrict__ mouth,
    const float* __restrict__ norm_w, const float* __restrict__ A,
    const float* __restrict__ inp_W, const float* __restrict__ Dlin_W,
    const float* __restrict__ fc1_W, const float* __restrict__ fc2_W)
{
    const int bid = blockIdx.x, t = threadIdx.x;
    if (bid < 128) {
        int warp = t >> 5, lane = t & 31;
        int r = bid * 8 + warp;
        const float* src = (r < HROWS) ? (x + (size_t)r * Dm)
                                       : (mouth + (size_t)(r - HROWS) * Dm);
        float4 v0 = ((const float4*)src)[lane * 2];
        float4 v1 = ((const float4*)src)[lane * 2 + 1];
        float s = v0.x * v0.x + v0.y * v0.y + v0.z * v0.z + v0.w * v0.w
                + v1.x * v1.x + v1.y * v1.y + v1.z * v1.z + v1.w * v1.w;
        #pragma unroll
        for (int o = 16; o; o >>= 1) s += __shfl_xor_sync(0xffffffffu, s, o);
        float rinv = 1.f / sqrtf(s + 1e-5f);
        float4 w0 = ((const float4*)norm_w)[lane * 2];
        float4 w1 = ((const float4*)norm_w)[lane * 2 + 1];
        v0.x *= rinv * w0.x; v0.y *= rinv * w0.y; v0.z *= rinv * w0.z; v0.w *= rinv * w0.w;
        v1.x *= rinv * w1.x; v1.y *= rinv * w1.y; v1.z *= rinv * w1.z; v1.w *= rinv * w1.w;
        *(uint4*)(g_XNbf + (size_t)r * Dm + lane * 8) = pack8(v0, v1);
    } else if (bid < 384) {
        int idx = (bid - 128) * 256 + t;   // d*128 + n, A is [D2][Sn]
        float a = A[idx];
        float e0 = exp2f(a);               // exp(ln2 * a)
        g_Ebf[0 * D2 * Sn + idx] = __float2bfloat16(e0);
        g_Ebf[1 * D2 * Sn + idx] = __float2bfloat16(a * e0);
        g_Ebf[2 * D2 * Sn + idx] = __float2bfloat16(0.5f * a * a * e0);
        g_Ebf[3 * D2 * Sn + idx] = __float2bfloat16((1.f / 6.f) * a * a * a * e0);
    } else {
        int wb = bid - 384;                // 0..287
        const float* src; __nv_bfloat16* dst; int base;
        if (wb < 64)       { src = inp_W;  dst = g_Wibf; base = wb * 2048; }
        else if (wb < 128) { src = Dlin_W; dst = g_Wdbf; base = (wb - 64) * 2048; }
        else if (wb < 256) { src = fc1_W;  dst = g_W1bf; base = (wb - 128) * 2048; }
        else               { src = fc2_W;  dst = g_W2bf; base = (wb - 256) * 2048; }
        int idx = base + t * 8;
        float4 u = ((const float4*)(src + idx))[0];
        float4 v = ((const float4*)(src + idx))[1];
        *(uint4*)(dst + idx) = pack8(u, v);
    }
}

// ---------------- bf16 cp.async GEMM core: C = A[64xK] @ W[NxK]^T + bias -----
// 64x64 tile, BK=32, 8 warps in 2(M) x 4(N), m16n8k16, 2-stage cp.async.
// CBF16: 1 -> C is bf16, 0 -> C fp32. ACT: 0 none, 1 silu, 2 softplus.
template<int ACT, int CBF16>
__device__ __forceinline__ void gemm_core_async(
    uint32_t* sm,   // 2 stages x 2 tiles x STGW words
    const __nv_bfloat16* __restrict__ A_t,   // tile row0, stride K
    const __nv_bfloat16* __restrict__ W,     // [N x K]
    const float* __restrict__ bias, void* Cv,
    int N, int K, int row0, int col0)
{
    const int t = threadIdx.x;
    const int lane = t & 31, warp = t >> 5;
    const int wm = warp & 1, wn = warp >> 1;
    const int g = lane >> 2, tig = lane & 3;
    const int ar = t >> 2, ac = (t & 3) * 8;
    const int ntiles = K >> 5;
    const uint32_t sbase = (uint32_t)__cvta_generic_to_shared(sm);
    const uint32_t doff = (uint32_t)(ar * SROW + (t & 3) * 4) * 4u;

    const __nv_bfloat16* Ap = A_t + (size_t)ar * K + ac;
    const __nv_bfloat16* Wp = W + (size_t)(col0 + ar) * K + ac;

    // prologue: stage 0
    cpa16(sbase + doff, Ap);
    cpa16(sbase + STGW * 4 + doff, Wp);
    CP_COMMIT();

    float c[2][2][4] = {};

    for (int kt = 0; kt < ntiles; kt++) {
        if (kt + 1 < ntiles) {
            uint32_t nb = sbase + (((kt + 1) & 1) * 2 * STGW) * 4 + doff;
            cpa16(nb, Ap + (kt + 1) * 32);
            cpa16(nb + STGW * 4, Wp + (kt + 1) * 32);
        }
        CP_COMMIT();
        CP_WAIT1();
        __syncthreads();
        uint32_t* As = sm + (kt & 1) * 2 * STGW;
        uint32_t* Bs = As + STGW;
        #pragma unroll
        for (int k16 = 0; k16 < 2; k16++) {
            const int kb = k16 * 8;
            uint32_t afr[2][4], bfr[2][2];
            #pragma unroll
            for (int mi = 0; mi < 2; mi++) {
                int r = wm * 32 + mi * 16 + g;
                afr[mi][0] = As[r * SROW + kb + tig];
                afr[mi][1] = As[(r + 8) * SROW + kb + tig];
                afr[mi][2] = As[r * SROW + kb + tig + 4];
                afr[mi][3] = As[(r + 8) * SROW + kb + tig + 4];
            }
            #pragma unroll
            for (int ni = 0; ni < 2; ni++) {
                int n = wn * 16 + ni * 8 + g;
                bfr[ni][0] = Bs[n * SROW + kb + tig];
                bfr[ni][1] = Bs[n * SROW + kb + tig + 4];
            }
            #pragma unroll
            for (int mi = 0; mi < 2; mi++)
                #pragma unroll
                for (int ni = 0; ni < 2; ni++)
                    mma_bf16(c[mi][ni], afr[mi][0], afr[mi][1], afr[mi][2],
                             afr[mi][3], bfr[ni][0], bfr[ni][1]);
        }
        __syncthreads();
    }

    #pragma unroll
    for (int mi = 0; mi < 2; mi++) {
        int r = row0 + wm * 32 + mi * 16 + g;
        #pragma unroll
        for (int ni = 0; ni < 2; ni++) {
            int n = col0 + wn * 16 + ni * 8 + 2 * tig;
            float b0 = bias[n], b1 = bias[n + 1];
            float v0 = c[mi][ni][0] + b0, v1 = c[mi][ni][1] + b1;
            float v2 = c[mi][ni][2] + b0, v3 = c[mi][ni][3] + b1;
            if (ACT == 1) { v0 = silu_f(v0); v1 = silu_f(v1); v2 = silu_f(v2); v3 = silu_f(v3); }
            else if (ACT == 2) { v0 = softplus_f(v0); v1 = softplus_f(v1); v2 = softplus_f(v2); v3 = softplus_f(v3); }
            if (CBF16) {
                __nv_bfloat16* Cb = (__nv_bfloat16*)Cv;
                *(uint32_t*)(Cb + (size_t)r * N + n) = pk(v0, v1);
                *(uint32_t*)(Cb + (size_t)(r + 8) * N + n) = pk(v2, v3);
            } else {
                float* Cf = (float*)Cv;
                *(float2*)&Cf[(size_t)r * N + n] = make_float2(v0, v1);
                *(float2*)&Cf[(size_t)(r + 8) * N + n] = make_float2(v2, v3);
            }
        }
    }
}

// ---------------- mega1: inp GEMM (0..127) + res GEMM (128..191) -------------
__global__ __launch_bounds__(256) void mega1_kernel(
    const float* __restrict__ inp_b, const float* __restrict__ Dlin_b)
{
    __shared__ uint32_t sm[2 * 2 * STGW];
    const int bid = blockIdx.x;
    if (bid < 128) {
        int by = bid >> 3, bx = bid & 7;
        int row0 = by * 64, col0 = bx * 64;
        gemm_core_async<0, 1>(sm, g_XNbf + (size_t)row0 * Dm, g_Wibf,
                              inp_b, g_Pbf, D2, Dm, row0, col0);
    } else {
        int b2 = bid - 128;
        int by = b2 >> 3, bx = b2 & 7;
        int row0 = by * 64, col0 = bx * 64;
        gemm_core_async<1, 0>(sm, g_XNbf + (size_t)row0 * Dm, g_Wdbf,
                              Dlin_b, g_RES, D2, Dm, row0, col0);
    }
}

// ---------------- conv 3x3 SAME + silu, h-tile = 4, bf16 in/out --------------
__global__ __launch_bounds__(256) void conv_silu_kernel(
    const float* __restrict__ cw, const float* __restrict__ cb)
{
    const int bid = blockIdx.x;          // 0..127
    const int T = bid >> 6;              // 0..1 (x / mouth)
    const int h0 = (bid & 63) * 4;       // output rows h0..h0+3
    __shared__ float rows[2][6][520];
    __shared__ float wsh[36];
    __shared__ float bsh[2];
    const int t = threadIdx.x;
    if (t < 36) wsh[t] = cw[t];          // [o][i][kh][kw]
    if (t < 2) bsh[t] = cb[t];
    const __nv_bfloat16* Pb = g_Pbf + (size_t)T * HROWS * D2;

    // load 2 channels x 6 rows (h0-1 .. h0+4), zero-padded; 8 bf16 per chunk
    for (int idx = t; idx < 2 * 6 * 64; idx += 256) {
        int i = idx / 384;
        int rem = idx - i * 384;
        int r = rem >> 6;                // 0..5
        int c8 = rem & 63;
        int hh = h0 + r - 1;
        float4 f0 = make_float4(0.f, 0.f, 0.f, 0.f), f1 = f0;
        if (hh >= 0 && hh < Lh) {
            uint4 q = *(const uint4*)(Pb + (size_t)(i * Lh + hh) * D2 + c8 * 8);
            const __nv_bfloat162* h = (const __nv_bfloat162*)&q;
            float2 a0 = __bfloat1622float2(h[0]), a1 = __bfloat1622float2(h[1]);
            float2 a2 = __bfloat1622float2(h[2]), a3 = __bfloat1622float2(h[3]);
            f0 = make_float4(a0.x, a0.y, a1.x, a1.y);
            f1 = make_float4(a2.x, a2.y, a3.x, a3.y);
        }
        *(float4*)&rows[i][r][c8 * 8] = f0;
        *(float4*)&rows[i][r][c8 * 8 + 4] = f1;
    }
    __syncthreads();

    #pragma unroll
    for (int oh = 0; oh < 4; oh++) {
        #pragma unroll
        for (int ws = 0; ws < 2; ws++) {
            int w = t + ws * 256;
            float acc0 = bsh[0], acc1 = bsh[1];
            #pragma unroll
            for (int i = 0; i < 2; i++)
                #pragma unroll
                for (int kh = 0; kh < 3; kh++) {
                    float dl = (w == 0)      ? 0.f : rows[i][oh + kh][w - 1];
                    float dc = rows[i][oh + kh][w];
                    float dr = (w == D2 - 1) ? 0.f : rows[i][oh + kh][w + 1];
                    acc0 += dl * wsh[i * 9 + kh * 3 + 0]
                          + dc * wsh[i * 9 + kh * 3 + 1]
                          + dr * wsh[i * 9 + kh * 3 + 2];
                    acc1 += dl * wsh[18 + i * 9 + kh * 3 + 0]
                          + dc * wsh[18 + i * 9 + kh * 3 + 1]
                          + dr * wsh[18 + i * 9 + kh * 3 + 2];
                }
            int h = h0 + oh;
            g_XCbf[((size_t)T * HROWS + 0 * Lh + h) * D2 + w] = __float2bfloat16(silu_f(acc0));
            g_XCbf[((size_t)T * HROWS + 1 * Lh + h) * D2 + w] = __float2bfloat16(silu_f(acc1));
        }
    }
}

// ---------------- mega2: delta GEMM (0..127) + Bm GEMM (128..159) ------------
__global__ __launch_bounds__(256) void mega2_kernel(
    const float* __restrict__ fc1_b, const float* __restrict__ fc2_b)
{
    __shared__ uint32_t sm[2 * 2 * STGW];
    const int bid = blockIdx.x;
    if (bid < 128) {
        int by = bid >> 3, bx = bid & 7;
        int row0 = by * 64, col0 = bx * 64;
        gemm_core_async<2, 0>(sm, g_XCbf + (size_t)row0 * D2, g_W1bf,
                              fc1_b, g_DELTA, D2, D2, row0, col0);
    } else {
        int b2 = bid - 128;               // 0..31
        int by = b2 >> 1, bx = b2 & 1;
        int row0 = by * 64, col0 = bx * 64;
        gemm_core_async<0, 1>(sm, g_XCbf + (size_t)row0 * D2, g_W2bf,
                              fc2_b, g_BMbf, Sn, D2, row0, col0);
    }
}

// ---------------- SSM: 4-slab bf16 cp.async GEMM + S2 + Horner + silu --------
// dynamic smem: 2 stages x 5 tiles (A + 4 E slabs) x STGW words = 51200 B
__global__ __launch_bounds__(256) void ssm_kernel()
{
    extern __shared__ uint32_t dsm[];
    __shared__ float s2s[64];
    const int t = threadIdx.x;
    const int lane = t & 31, warp = t >> 5;
    const int wm = warp & 1, wn = warp >> 1;
    const int g = lane >> 2, tig = lane & 3;
    const int row0 = blockIdx.y * 64, col0 = blockIdx.x * 64;
    const int ar = t >> 2, ac = (t & 3) * 8;
    const uint32_t sbase = (uint32_t)__cvta_generic_to_shared(dsm);
    const uint32_t doff = (uint32_t)(ar * SROW + (t & 3) * 4) * 4u;

    const __nv_bfloat16* Ap = g_BMbf + (size_t)(row0 + ar) * Sn + ac;

    // prologue: stage 0 (kt=0)
    {
        uint32_t sb = sbase + doff;
        cpa16(sb, Ap);
        #pragma unroll
        for (int j = 0; j < 4; j++)
            cpa16(sb + (1 + j) * STGW * 4,
                  g_Ebf + (size_t)(j * D2 + col0 + ar) * Sn + ac);
    }
    CP_COMMIT();

    if (t < 64) s2s[t] = 0.f;
    // per-row sum of Bm^2 from bf16: 4 threads/row, 32 elems each
    float s2p = 0.f;
    {
        const uint4* bm = (const uint4*)(g_BMbf + (size_t)(row0 + (t >> 2)) * Sn
                                         + (t & 3) * 32);
        #pragma unroll
        for (int i = 0; i < 4; i++) {
            uint4 q = bm[i];
            const __nv_bfloat162* h = (const __nv_bfloat162*)&q;
            #pragma unroll
            for (int p = 0; p < 4; p++) {
                float2 f = __bfloat1622float2(h[p]);
                s2p += f.x * f.x + f.y * f.y;
            }
        }
    }
    __syncthreads();
    atomicAdd(&s2s[t >> 2], s2p);

    float c[4][2][2][4] = {};

    for (int kt = 0; kt < 4; kt++) {
        if (kt + 1 < 4) {
            uint32_t sb = sbase + (((kt + 1) & 1) * 5 * STGW) * 4 + doff;
            cpa16(sb, Ap + (kt + 1) * 32);
            #pragma unroll
            for (int j = 0; j < 4; j++)
                cpa16(sb + (1 + j) * STGW * 4,
                      g_Ebf + (size_t)(j * D2 + col0 + ar) * Sn + (kt + 1) * 32 + ac);
        }
        CP_COMMIT();
        CP_WAIT1();
        __syncthreads();
        uint32_t* As = dsm + (kt & 1) * 5 * STGW;
        #pragma unroll
        for (int k16 = 0; k16 < 2; k16++) {
            const int kb = k16 * 8;
            uint32_t afr[2][4];
            #pragma unroll
            for (int mi = 0; mi < 2; mi++) {
                int r = wm * 32 + mi * 16 + g;
                afr[mi][0] = As[r * SROW + kb + tig];
                afr[mi][1] = As[(r + 8) * SROW + kb + tig];
                afr[mi][2] = As[r * SROW + kb + tig + 4];
                afr[mi][3] = As[(r + 8) * SROW + kb + tig + 4];
            }
            #pragma unroll
            for (int j = 0; j < 4; j++) {
                const uint32_t* Es = As + (1 + j) * STGW;
                uint32_t bfr[2][2];
                #pragma unroll
                for (int ni = 0; ni < 2; ni++) {
                    int n = wn * 16 + ni * 8 + g;
                    bfr[ni][0] = Es[n * SROW + kb + tig];
                    bfr[ni][1] = Es[n * SROW + kb + tig + 4];
                }
                #pragma unroll
                for (int mi = 0; mi < 2; mi++)
                    #pragma unroll
                    for (int ni = 0; ni < 2; ni++)
                        mma_bf16(c[j][mi][ni], afr[mi][0], afr[mi][1], afr[mi][2],
                                 afr[mi][3], bfr[ni][0], bfr[ni][1]);
            }
        }
        __syncthreads();
    }

    // epilogue: Horner in u + x*delta*S2, then silu
    #pragma unroll
    for (int mi = 0; mi < 2; mi++) {
        #pragma unroll
        for (int half = 0; half < 2; half++) {
            int rl = wm * 32 + mi * 16 + g + half * 8;
            int r = row0 + rl;
            float s2 = s2s[rl];
            #pragma unroll
            for (int ni = 0; ni < 2; ni++) {
                int d = col0 + wn * 16 + ni * 8 + 2 * tig;
                float2 dl = *(const float2*)&g_DELTA[(size_t)r * D2 + d];
                float2 xc = __bfloat1622float2(
                    *(const __nv_bfloat162*)(g_XCbf + (size_t)r * D2 + d));
                int q0 = half * 2;
                float u0 = dl.x - LN2F, u1 = dl.y - LN2F;
                float s0 = c[0][mi][ni][q0]
                         + u0 * (c[1][mi][ni][q0] + u0 * (c[2][mi][ni][q0] + u0 * c[3][mi][ni][q0]));
                float s1 = c[0][mi][ni][q0 + 1]
                         + u1 * (c[1][mi][ni][q0 + 1] + u1 * (c[2][mi][ni][q0 + 1] + u1 * c[3][mi][ni][q0 + 1]));
                s0 += xc.x * dl.x * s2;
                s1 += xc.y * dl.y * s2;
                *(float2*)&g_XS[(size_t)r * D2 + d] = make_float2(silu_f(s0), silu_f(s1));
            }
        }
    }
}

// ---------------- out GEMM with fused comb (register-staged, fp32 inputs) ----
__global__ __launch_bounds__(256) void out_kernel(
    const float* __restrict__ out_W, const float* __restrict__ out_b,
    float* __restrict__ out)
{
    __shared__ uint32_t smbuf[2 * STGW];
    uint32_t* As = smbuf;
    uint32_t* Bs = smbuf + STGW;
    const int t = threadIdx.x;
    const int lane = t & 31, warp = t >> 5;
    const int wm = warp & 1, wn = warp >> 1;
    const int g = lane >> 2, tig = lane & 3;
    const int row0 = blockIdx.y * 64, col0 = blockIdx.x * 64;
    const int ar = t >> 2, ac = (t & 3) * 8;
    const int N = Dm, K = D2;

    const float* Ap  = g_XS + (size_t)(row0 + ar) * K + ac;
    const float* A2p = g_XS + (size_t)(HROWS + row0 + ar) * K + ac;
    const float* A3p = g_RES + (size_t)(row0 + ar) * K + ac;
    const float* Wp  = out_W + (size_t)(col0 + ar) * K + ac;

    float c[2][2][4] = {};
    const int ntiles = K >> 5;
    uint4 ab, wb;

#define LOAD_AB(ko) do { \
    float4 u = *(const float4*)(Ap + (ko)); \
    float4 v = *(const float4*)(Ap + (ko) + 4); \
    float4 u2 = *(const float4*)(A2p + (ko)), u3 = *(const float4*)(A3p + (ko)); \
    float4 v2 = *(const float4*)(A2p + (ko) + 4), v3 = *(const float4*)(A3p + (ko) + 4); \
    u.x = (u.x + u2.x) * u3.x; u.y = (u.y + u2.y) * u3.y; \
    u.z = (u.z + u2.z) * u3.z; u.w = (u.w + u2.w) * u3.w; \
    v.x = (v.x + v2.x) * v3.x; v.y = (v.y + v2.y) * v3.y; \
    v.z = (v.z + v2.z) * v3.z; v.w = (v.w + v2.w) * v3.w; \
    ab = pack8(u, v); \
    float4 xx = *(const float4*)(Wp + (ko)); \
    float4 yy = *(const float4*)(Wp + (ko) + 4); \
    wb = pack8(xx, yy); \
} while (0)

    LOAD_AB(0);
    for (int kt = 0; kt < ntiles; kt++) {
        __syncthreads();
        *(uint4*)&As[ar * SROW + (t & 3) * 4] = ab;
        *(uint4*)&Bs[ar * SROW + (t & 3) * 4] = wb;
        __syncthreads();
        if (kt + 1 < ntiles) LOAD_AB((kt + 1) * 32);
        #pragma unroll
        for (int k16 = 0; k16 < 2; k16++) {
            const int kb = k16 * 8;
            uint32_t afr[2][4], bfr[2][2];
            #pragma unroll
            for (int mi = 0; mi < 2; mi++) {
                int r = wm * 32 + mi * 16 + g;
                afr[mi][0] = As[r * SROW + kb + tig];
                afr[mi][1] = As[(r + 8) * SROW + kb + tig];
                afr[mi][2] = As[r * SROW + kb + tig + 4];
                afr[mi][3] = As[(r + 8) * SROW + kb + tig + 4];
            }
            #pragma unroll
            for (int ni = 0; ni < 2; ni++) {
                int n = wn * 16 + ni * 8 + g;
                bfr[ni][0] = Bs[n * SROW + kb + tig];
                bfr[ni][1] = Bs[n * SROW + kb + tig + 4];
            }
            #pragma unroll
            for (int mi = 0; mi < 2; mi++)
                #pragma unroll
                for (int ni = 0; ni < 2; ni++)
                    mma_bf16(c[mi][ni], afr[mi][0], afr[mi][1], afr[mi][2],
                             afr[mi][3], bfr[ni][0], bfr[ni][1]);
        }
    }
#undef LOAD_AB

    #pragma unroll
    for (int mi = 0; mi < 2; mi++) {
        int r = row0 + wm * 32 + mi * 16 + g;
        #pragma unroll
        for (int ni = 0; ni < 2; ni++) {
            int n = col0 + wn * 16 + ni * 8 + 2 * tig;
            float b0 = out_b[n], b1 = out_b[n + 1];
            *(float2*)&out[(size_t)r * N + n] =
                make_float2(c[mi][ni][0] + b0, c[mi][ni][1] + b1);
            *(float2*)&out[(size_t)(r + 8) * N + n] =
                make_float2(c[mi][ni][2] + b0, c[mi][ni][3] + b1);
        }
    }
}

// ---------------- launch ----------------
extern "C" void kernel_launch(void* const* d_in, const int* in_sizes, int n_in,
                              void* d_out, int out_size)
{
    const float* x      = (const float*)d_in[0];
    const float* mouth  = (const float*)d_in[1];
    const float* norm_w = (const float*)d_in[2];
    const float* inp_W  = (const float*)d_in[3];
    const float* inp_b  = (const float*)d_in[4];
    const float* out_W  = (const float*)d_in[5];
    const float* out_b  = (const float*)d_in[6];
    const float* Dlin_W = (const float*)d_in[7];
    const float* Dlin_b = (const float*)d_in[8];
    const float* conv_W = (const float*)d_in[9];
    const float* conv_b = (const float*)d_in[10];
    const float* fc1_W  = (const float*)d_in[11];
    const float* fc1_b  = (const float*)d_in[12];
    const float* fc2_W  = (const float*)d_in[13];
    const float* fc2_b  = (const float*)d_in[14];
    const float* A      = (const float*)d_in[15];

    const int SSM_SMEM = 2 * 5 * STGW * 4;   // 51200 B
    cudaFuncSetAttribute(ssm_kernel,
                         cudaFuncAttributeMaxDynamicSharedMemorySize, SSM_SMEM);

    // 1) XNbf + E bf16 + weight bf16
    prep_kernel<<<672, 256>>>(x, mouth, norm_w, A, inp_W, Dlin_W, fc1_W, fc2_W);
    // 2) inp GEMM -> Pbf, res GEMM -> RES
    mega1_kernel<<<192, 256>>>(inp_b, Dlin_b);
    // 3) conv + silu -> XCbf
    conv_silu_kernel<<<128, 256>>>(conv_W, conv_b);
    // 4) delta GEMM -> DELTA, Bm GEMM -> BMbf
    mega2_kernel<<<160, 256>>>(fc1_b, fc2_b);
    // 5) ssm (4-slab GEMM + S2 + Horner + silu) -> XS
    ssm_kernel<<<dim3(D2 / 64, NROWS / 64), 256, SSM_SMEM>>>();
    // 6) out = ((XS_x + XS_m) * RES) @ out_W^T + out_b
    out_kernel<<<dim3(Dm / 64, HROWS / 64), 256>>>(out_W, out_b, (float*)d_out);
}

// round 12
// speedup vs baseline: 3.2027x; 1.0500x over previous
#include <cuda_runtime.h>
#include <cuda_bf16.h>
#include <math.h>
#include <stdint.h>

// Problem constants
#define Dm     256
#define D2     512
#define Sn     128
#define Lh     256
#define NROWS  1024   // (x rows 0..511) + (mouth rows 512..1023)
#define HROWS  512
#define LN2F   0.69314718055994531f
#define SROW   20                 // smem row stride in uint32 words
#define A32W   (32 * SROW)        // words per 32x32-bf16 tile
#define B64W   (64 * SROW)        // words per 64x32-bf16 tile
#define GSTAGE (A32W + B64W)      // per-stage words for gemm32 core

// ---------------- scratch (static __device__, no allocations) ----------------
__device__ __nv_bfloat16 g_XNbf[NROWS * Dm];   // rmsnormed x|mouth (bf16)
__device__ __nv_bfloat16 g_Wibf[D2 * Dm];      // inp_W bf16
__device__ __nv_bfloat16 g_Wdbf[D2 * Dm];      // Dlin_W bf16
__device__ __nv_bfloat16 g_W1bf[D2 * D2];      // fc1_W bf16
__device__ __nv_bfloat16 g_W2bf[Sn * D2];      // fc2_W bf16
__device__ __nv_bfloat16 g_Pbf[NROWS * D2];    // inp projection (bf16)
__device__ __nv_bfloat16 g_XCbf[NROWS * D2];   // silu(conv(P)) (bf16)
__device__ float         g_DELTA[NROWS * D2];  // softplus(fc1) (fp32)
__device__ __nv_bfloat16 g_BMbf[NROWS * Sn];   // fc2 (bf16)
__device__ __nv_bfloat16 g_Ebf[4 * D2 * Sn];   // E_j[d][n] = A^j 2^A / j! (bf16)
__device__ float         g_XS[NROWS * D2];     // silu(ssm) (fp32)
__device__ float         g_RES[HROWS * D2];    // silu(Dlin(x_n)) (fp32)

__device__ __forceinline__ float silu_f(float v) { return v / (1.f + expf(-v)); }
__device__ __forceinline__ float softplus_f(float v) {
    return fmaxf(v, 0.f) + log1pf(expf(-fabsf(v)));
}
__device__ __forceinline__ uint32_t pk(float a, float b) {
    __nv_bfloat162 h = __floats2bfloat162_rn(a, b);
    return *reinterpret_cast<uint32_t*>(&h);
}
__device__ __forceinline__ uint4 pack8(float4 u, float4 v) {
    return make_uint4(pk(u.x, u.y), pk(u.z, u.w), pk(v.x, v.y), pk(v.z, v.w));
}
__device__ __forceinline__ void mma_bf16(float c[4],
    uint32_t a0, uint32_t a1, uint32_t a2, uint32_t a3,
    uint32_t b0, uint32_t b1)
{
    asm("mma.sync.aligned.m16n8k16.row.col.f32.bf16.bf16.f32 "
        "{%0,%1,%2,%3}, {%4,%5,%6,%7}, {%8,%9}, {%0,%1,%2,%3};"
        : "+f"(c[0]), "+f"(c[1]), "+f"(c[2]), "+f"(c[3])
        : "r"(a0), "r"(a1), "r"(a2), "r"(a3), "r"(b0), "r"(b1));
}
__device__ __forceinline__ void cpa16(uint32_t saddr, const void* g) {
    asm volatile("cp.async.ca.shared.global [%0], [%1], 16;"
                 :: "r"(saddr), "l"(g) : "memory");
}
#define CP_COMMIT() asm volatile("cp.async.commit_group;" ::: "memory")
#define CP_WAIT1()  asm volatile("cp.async.wait_group 1;" ::: "memory")

// ---------------- prep: XNbf + E slabs + weight->bf16 ------------------------
__global__ __launch_bounds__(256) void prep_kernel(
    const float* __restrict__ x, const float* __restrict__ mouth,
    const float* __restrict__ norm_w, const float* __restrict__ A,
    const float* __restrict__ inp_W, const float* __restrict__ Dlin_W,
    const float* __restrict__ fc1_W, const float* __restrict__ fc2_W)
{
    const int bid = blockIdx.x, t = threadIdx.x;
    if (bid < 128) {
        int warp = t >> 5, lane = t & 31;
        int r = bid * 8 + warp;
        const float* src = (r < HROWS) ? (x + (size_t)r * Dm)
                                       : (mouth + (size_t)(r - HROWS) * Dm);
        float4 v0 = ((const float4*)src)[lane * 2];
        float4 v1 = ((const float4*)src)[lane * 2 + 1];
        float s = v0.x * v0.x + v0.y * v0.y + v0.z * v0.z + v0.w * v0.w
                + v1.x * v1.x + v1.y * v1.y + v1.z * v1.z + v1.w * v1.w;
        #pragma unroll
        for (int o = 16; o; o >>= 1) s += __shfl_xor_sync(0xffffffffu, s, o);
        float rinv = 1.f / sqrtf(s + 1e-5f);
        float4 w0 = ((const float4*)norm_w)[lane * 2];
        float4 w1 = ((const float4*)norm_w)[lane * 2 + 1];
        v0.x *= rinv * w0.x; v0.y *= rinv * w0.y; v0.z *= rinv * w0.z; v0.w *= rinv * w0.w;
        v1.x *= rinv * w1.x; v1.y *= rinv * w1.y; v1.z *= rinv * w1.z; v1.w *= rinv * w1.w;
        *(uint4*)(g_XNbf + (size_t)r * Dm + lane * 8) = pack8(v0, v1);
    } else if (bid < 384) {
        int idx = (bid - 128) * 256 + t;   // d*128 + n, A is [D2][Sn]
        float a = A[idx];
        float e0 = exp2f(a);               // exp(ln2 * a)
        g_Ebf[0 * D2 * Sn + idx] = __float2bfloat16(e0);
        g_Ebf[1 * D2 * Sn + idx] = __float2bfloat16(a * e0);
        g_Ebf[2 * D2 * Sn + idx] = __float2bfloat16(0.5f * a * a * e0);
        g_Ebf[3 * D2 * Sn + idx] = __float2bfloat16((1.f / 6.f) * a * a * a * e0);
    } else {
        int wb = bid - 384;                // 0..287
        const float* src; __nv_bfloat16* dst; int base;
        if (wb < 64)       { src = inp_W;  dst = g_Wibf; base = wb * 2048; }
        else if (wb < 128) { src = Dlin_W; dst = g_Wdbf; base = (wb - 64) * 2048; }
        else if (wb < 256) { src = fc1_W;  dst = g_W1bf; base = (wb - 128) * 2048; }
        else               { src = fc2_W;  dst = g_W2bf; base = (wb - 256) * 2048; }
        int idx = base + t * 8;
        float4 u = ((const float4*)(src + idx))[0];
        float4 v = ((const float4*)(src + idx))[1];
        *(uint4*)(dst + idx) = pack8(u, v);
    }
}

// ---------------- bf16 cp.async GEMM core: 32x64 tile, 128 thr, 4 warps ------
// C = A[32 x K] @ W[N x K]^T + bias ; BK=32, 2-stage cp.async, m16n8k16.
// warp wn (0..3) covers cols wn*16..wn*16+15; rows via 2 m-frags of 16.
// CBF16: 1 -> C bf16, 0 -> fp32. ACT: 0 none, 1 silu, 2 softplus.
template<int ACT, int CBF16>
__device__ __forceinline__ void gemm32_core(
    uint32_t* sm,   // 2 * GSTAGE words
    const __nv_bfloat16* __restrict__ A_t,   // tile row0, stride K
    const __nv_bfloat16* __restrict__ W,     // [N x K]
    const float* __restrict__ bias, void* Cv,
    int N, int K, int row0, int col0)
{
    const int t = threadIdx.x;
    const int lane = t & 31, wn = t >> 5;
    const int g = lane >> 2, tig = lane & 3;
    const int ar = t >> 2, ac = (t & 3) * 8;
    const int ntiles = K >> 5;
    const uint32_t sbase = (uint32_t)__cvta_generic_to_shared(sm);
    const uint32_t aoff = (uint32_t)(ar * SROW + (t & 3) * 4) * 4u;

    const __nv_bfloat16* Ap  = A_t + (size_t)ar * K + ac;
    const __nv_bfloat16* Wp0 = W + (size_t)(col0 + ar) * K + ac;
    const __nv_bfloat16* Wp1 = W + (size_t)(col0 + ar + 32) * K + ac;

    // prologue: stage 0
    cpa16(sbase + aoff, Ap);
    cpa16(sbase + A32W * 4 + aoff, Wp0);
    cpa16(sbase + (A32W + 32 * SROW) * 4 + aoff, Wp1);
    CP_COMMIT();

    float c[2][2][4] = {};

    for (int kt = 0; kt < ntiles; kt++) {
        if (kt + 1 < ntiles) {
            uint32_t nb = sbase + (((kt + 1) & 1) * GSTAGE) * 4 + aoff;
            cpa16(nb, Ap + (kt + 1) * 32);
            cpa16(nb + A32W * 4, Wp0 + (kt + 1) * 32);
            cpa16(nb + (A32W + 32 * SROW) * 4, Wp1 + (kt + 1) * 32);
        }
        CP_COMMIT();
        CP_WAIT1();
        __syncthreads();
        uint32_t* As = sm + (kt & 1) * GSTAGE;
        uint32_t* Bs = As + A32W;
        #pragma unroll
        for (int k16 = 0; k16 < 2; k16++) {
            const int kb = k16 * 8;
            uint32_t afr[2][4], bfr[2][2];
            #pragma unroll
            for (int mi = 0; mi < 2; mi++) {
                int r = mi * 16 + g;
                afr[mi][0] = As[r * SROW + kb + tig];
                afr[mi][1] = As[(r + 8) * SROW + kb + tig];
                afr[mi][2] = As[r * SROW + kb + tig + 4];
                afr[mi][3] = As[(r + 8) * SROW + kb + tig + 4];
            }
            #pragma unroll
            for (int ni = 0; ni < 2; ni++) {
                int n = wn * 16 + ni * 8 + g;
                bfr[ni][0] = Bs[n * SROW + kb + tig];
                bfr[ni][1] = Bs[n * SROW + kb + tig + 4];
            }
            #pragma unroll
            for (int mi = 0; mi < 2; mi++)
                #pragma unroll
                for (int ni = 0; ni < 2; ni++)
                    mma_bf16(c[mi][ni], afr[mi][0], afr[mi][1], afr[mi][2],
                             afr[mi][3], bfr[ni][0], bfr[ni][1]);
        }
        __syncthreads();
    }

    #pragma unroll
    for (int mi = 0; mi < 2; mi++) {
        int r = row0 + mi * 16 + g;
        #pragma unroll
        for (int ni = 0; ni < 2; ni++) {
            int n = col0 + wn * 16 + ni * 8 + 2 * tig;
            float b0 = bias[n], b1 = bias[n + 1];
            float v0 = c[mi][ni][0] + b0, v1 = c[mi][ni][1] + b1;
            float v2 = c[mi][ni][2] + b0, v3 = c[mi][ni][3] + b1;
            if (ACT == 1) { v0 = silu_f(v0); v1 = silu_f(v1); v2 = silu_f(v2); v3 = silu_f(v3); }
            else if (ACT == 2) { v0 = softplus_f(v0); v1 = softplus_f(v1); v2 = softplus_f(v2); v3 = softplus_f(v3); }
            if (CBF16) {
                __nv_bfloat16* Cb = (__nv_bfloat16*)Cv;
                *(uint32_t*)(Cb + (size_t)r * N + n) = pk(v0, v1);
                *(uint32_t*)(Cb + (size_t)(r + 8) * N + n) = pk(v2, v3);
            } else {
                float* Cf = (float*)Cv;
                *(float2*)&Cf[(size_t)r * N + n] = make_float2(v0, v1);
                *(float2*)&Cf[(size_t)(r + 8) * N + n] = make_float2(v2, v3);
            }
        }
    }
}

// ---------------- mega1: inp GEMM (0..255) + res GEMM (256..383) -------------
__global__ __launch_bounds__(128) void mega1_kernel(
    const float* __restrict__ inp_b, const float* __restrict__ Dlin_b)
{
    __shared__ uint32_t sm[2 * GSTAGE];
    const int bid = blockIdx.x;
    if (bid < 256) {
        int by = bid >> 3, bx = bid & 7;
        int row0 = by * 32, col0 = bx * 64;
        gemm32_core<0, 1>(sm, g_XNbf + (size_t)row0 * Dm, g_Wibf,
                          inp_b, g_Pbf, D2, Dm, row0, col0);
    } else {
        int b2 = bid - 256;
        int by = b2 >> 3, bx = b2 & 7;
        int row0 = by * 32, col0 = bx * 64;
        gemm32_core<1, 0>(sm, g_XNbf + (size_t)row0 * Dm, g_Wdbf,
                          Dlin_b, g_RES, D2, Dm, row0, col0);
    }
}

// ---------------- conv 3x3 SAME + silu, h-tile = 4, bf16 in/out --------------
__global__ __launch_bounds__(256) void conv_silu_kernel(
    const float* __restrict__ cw, const float* __restrict__ cb)
{
    const int bid = blockIdx.x;          // 0..127
    const int T = bid >> 6;              // 0..1 (x / mouth)
    const int h0 = (bid & 63) * 4;       // output rows h0..h0+3
    __shared__ float rows[2][6][520];
    __shared__ float wsh[36];
    __shared__ float bsh[2];
    const int t = threadIdx.x;
    if (t < 36) wsh[t] = cw[t];          // [o][i][kh][kw]
    if (t < 2) bsh[t] = cb[t];
    const __nv_bfloat16* Pb = g_Pbf + (size_t)T * HROWS * D2;

    for (int idx = t; idx < 2 * 6 * 64; idx += 256) {
        int i = idx / 384;
        int rem = idx - i * 384;
        int r = rem >> 6;                // 0..5
        int c8 = rem & 63;
        int hh = h0 + r - 1;
        float4 f0 = make_float4(0.f, 0.f, 0.f, 0.f), f1 = f0;
        if (hh >= 0 && hh < Lh) {
            uint4 q = *(const uint4*)(Pb + (size_t)(i * Lh + hh) * D2 + c8 * 8);
            const __nv_bfloat162* h = (const __nv_bfloat162*)&q;
            float2 a0 = __bfloat1622float2(h[0]), a1 = __bfloat1622float2(h[1]);
            float2 a2 = __bfloat1622float2(h[2]), a3 = __bfloat1622float2(h[3]);
            f0 = make_float4(a0.x, a0.y, a1.x, a1.y);
            f1 = make_float4(a2.x, a2.y, a3.x, a3.y);
        }
        *(float4*)&rows[i][r][c8 * 8] = f0;
        *(float4*)&rows[i][r][c8 * 8 + 4] = f1;
    }
    __syncthreads();

    #pragma unroll
    for (int oh = 0; oh < 4; oh++) {
        #pragma unroll
        for (int ws = 0; ws < 2; ws++) {
            int w = t + ws * 256;
            float acc0 = bsh[0], acc1 = bsh[1];
            #pragma unroll
            for (int i = 0; i < 2; i++)
                #pragma unroll
                for (int kh = 0; kh < 3; kh++) {
                    float dl = (w == 0)      ? 0.f : rows[i][oh + kh][w - 1];
                    float dc = rows[i][oh + kh][w];
                    float dr = (w == D2 - 1) ? 0.f : rows[i][oh + kh][w + 1];
                    acc0 += dl * wsh[i * 9 + kh * 3 + 0]
                          + dc * wsh[i * 9 + kh * 3 + 1]
                          + dr * wsh[i * 9 + kh * 3 + 2];
                    acc1 += dl * wsh[18 + i * 9 + kh * 3 + 0]
                          + dc * wsh[18 + i * 9 + kh * 3 + 1]
                          + dr * wsh[18 + i * 9 + kh * 3 + 2];
                }
            int h = h0 + oh;
            g_XCbf[((size_t)T * HROWS + 0 * Lh + h) * D2 + w] = __float2bfloat16(silu_f(acc0));
            g_XCbf[((size_t)T * HROWS + 1 * Lh + h) * D2 + w] = __float2bfloat16(silu_f(acc1));
        }
    }
}

// ---------------- mega2: delta GEMM (0..255) + Bm GEMM (256..319) ------------
__global__ __launch_bounds__(128) void mega2_kernel(
    const float* __restrict__ fc1_b, const float* __restrict__ fc2_b)
{
    __shared__ uint32_t sm[2 * GSTAGE];
    const int bid = blockIdx.x;
    if (bid < 256) {
        int by = bid >> 3, bx = bid & 7;
        int row0 = by * 32, col0 = bx * 64;
        gemm32_core<2, 0>(sm, g_XCbf + (size_t)row0 * D2, g_W1bf,
                          fc1_b, g_DELTA, D2, D2, row0, col0);
    } else {
        int b2 = bid - 256;               // 0..63
        int by = b2 >> 1, bx = b2 & 1;
        int row0 = by * 32, col0 = bx * 64;
        gemm32_core<0, 1>(sm, g_XCbf + (size_t)row0 * D2, g_W2bf,
                          fc2_b, g_BMbf, Sn, D2, row0, col0);
    }
}

// ---------------- SSM: 4-slab bf16 cp.async GEMM + S2 + Horner + silu --------
// 32x64 tile; stage = A(32xSROW) + 4xE(64xSROW) words; 2 stages dynamic smem.
#define SSTAGE (A32W + 4 * B64W)
__global__ __launch_bounds__(128) void ssm_kernel()
{
    extern __shared__ uint32_t dsm[];
    __shared__ float s2s[32];
    const int t = threadIdx.x;
    const int lane = t & 31, wn = t >> 5;
    const int g = lane >> 2, tig = lane & 3;
    const int row0 = blockIdx.y * 32, col0 = blockIdx.x * 64;
    const int ar = t >> 2, ac = (t & 3) * 8;
    const uint32_t sbase = (uint32_t)__cvta_generic_to_shared(dsm);
    const uint32_t aoff = (uint32_t)(ar * SROW + (t & 3) * 4) * 4u;

    const __nv_bfloat16* Ap = g_BMbf + (size_t)(row0 + ar) * Sn + ac;

    // prologue: stage 0 (kt=0)
    {
        uint32_t sb = sbase + aoff;
        cpa16(sb, Ap);
        #pragma unroll
        for (int j = 0; j < 4; j++) {
            uint32_t eb = sb + (A32W + j * B64W) * 4;
            cpa16(eb, g_Ebf + (size_t)(j * D2 + col0 + ar) * Sn + ac);
            cpa16(eb + 32 * SROW * 4,
                  g_Ebf + (size_t)(j * D2 + col0 + ar + 32) * Sn + ac);
        }
    }
    CP_COMMIT();

    if (t < 32) s2s[t] = 0.f;
    // per-row sum of Bm^2 from bf16: 4 threads/row, 32 elems each
    float s2p = 0.f;
    {
        const uint4* bm = (const uint4*)(g_BMbf + (size_t)(row0 + (t >> 2)) * Sn
                                         + (t & 3) * 32);
        #pragma unroll
        for (int i = 0; i < 4; i++) {
            uint4 q = bm[i];
            const __nv_bfloat162* h = (const __nv_bfloat162*)&q;
            #pragma unroll
            for (int p = 0; p < 4; p++) {
                float2 f = __bfloat1622float2(h[p]);
                s2p += f.x * f.x + f.y * f.y;
            }
        }
    }
    __syncthreads();
    atomicAdd(&s2s[t >> 2], s2p);

    float c[4][2][2][4] = {};

    for (int kt = 0; kt < 4; kt++) {
        if (kt + 1 < 4) {
            uint32_t sb = sbase + (((kt + 1) & 1) * SSTAGE) * 4 + aoff;
            cpa16(sb, Ap + (kt + 1) * 32);
            #pragma unroll
            for (int j = 0; j < 4; j++) {
                uint32_t eb = sb + (A32W + j * B64W) * 4;
                cpa16(eb, g_Ebf + (size_t)(j * D2 + col0 + ar) * Sn + (kt + 1) * 32 + ac);
                cpa16(eb + 32 * SROW * 4,
                      g_Ebf + (size_t)(j * D2 + col0 + ar + 32) * Sn + (kt + 1) * 32 + ac);
            }
        }
        CP_COMMIT();
        CP_WAIT1();
        __syncthreads();
        uint32_t* As = dsm + (kt & 1) * SSTAGE;
        #pragma unroll
        for (int k16 = 0; k16 < 2; k16++) {
            const int kb = k16 * 8;
            uint32_t afr[2][4];
            #pragma unroll
            for (int mi = 0; mi < 2; mi++) {
                int r = mi * 16 + g;
                afr[mi][0] = As[r * SROW + kb + tig];
                afr[mi][1] = As[(r + 8) * SROW + kb + tig];
                afr[mi][2] = As[r * SROW + kb + tig + 4];
                afr[mi][3] = As[(r + 8) * SROW + kb + tig + 4];
            }
            #pragma unroll
            for (int j = 0; j < 4; j++) {
                const uint32_t* Es = As + A32W + j * B64W;
                uint32_t bfr[2][2];
                #pragma unroll
                for (int ni = 0; ni < 2; ni++) {
                    int n = wn * 16 + ni * 8 + g;
                    bfr[ni][0] = Es[n * SROW + kb + tig];
                    bfr[ni][1] = Es[n * SROW + kb + tig + 4];
                }
                #pragma unroll
                for (int mi = 0; mi < 2; mi++)
                    #pragma unroll
                    for (int ni = 0; ni < 2; ni++)
                        mma_bf16(c[j][mi][ni], afr[mi][0], afr[mi][1], afr[mi][2],
                                 afr[mi][3], bfr[ni][0], bfr[ni][1]);
            }
        }
        __syncthreads();
    }

    // epilogue: Horner in u + x*delta*S2, then silu
    #pragma unroll
    for (int mi = 0; mi < 2; mi++) {
        #pragma unroll
        for (int half = 0; half < 2; half++) {
            int rl = mi * 16 + g + half * 8;
            int r = row0 + rl;
            float s2 = s2s[rl];
            #pragma unroll
            for (int ni = 0; ni < 2; ni++) {
                int d = col0 + wn * 16 + ni * 8 + 2 * tig;
                float2 dl = *(const float2*)&g_DELTA[(size_t)r * D2 + d];
                float2 xc = __bfloat1622float2(
                    *(const __nv_bfloat162*)(g_XCbf + (size_t)r * D2 + d));
                int q0 = half * 2;
                float u0 = dl.x - LN2F, u1 = dl.y - LN2F;
                float s0 = c[0][mi][ni][q0]
                         + u0 * (c[1][mi][ni][q0] + u0 * (c[2][mi][ni][q0] + u0 * c[3][mi][ni][q0]));
                float s1 = c[0][mi][ni][q0 + 1]
                         + u1 * (c[1][mi][ni][q0 + 1] + u1 * (c[2][mi][ni][q0 + 1] + u1 * c[3][mi][ni][q0 + 1]));
                s0 += xc.x * dl.x * s2;
                s1 += xc.y * dl.y * s2;
                *(float2*)&g_XS[(size_t)r * D2 + d] = make_float2(silu_f(s0), silu_f(s1));
            }
        }
    }
}

// ---------------- out GEMM with fused comb (register-staged, fp32 inputs) ----
__global__ __launch_bounds__(128) void out_kernel(
    const float* __restrict__ out_W, const float* __restrict__ out_b,
    float* __restrict__ out)
{
    __shared__ uint32_t smbuf[A32W + B64W];
    uint32_t* As = smbuf;
    uint32_t* Bs = smbuf + A32W;
    const int t = threadIdx.x;
    const int lane = t & 31, wn = t >> 5;
    const int g = lane >> 2, tig = lane & 3;
    const int row0 = blockIdx.y * 32, col0 = blockIdx.x * 64;
    const int ar = t >> 2, ac = (t & 3) * 8;
    const int N = Dm, K = D2;

    const float* Ap  = g_XS + (size_t)(row0 + ar) * K + ac;
    const float* A2p = g_XS + (size_t)(HROWS + row0 + ar) * K + ac;
    const float* A3p = g_RES + (size_t)(row0 + ar) * K + ac;
    const float* Wp0 = out_W + (size_t)(col0 + ar) * K + ac;
    const float* Wp1 = out_W + (size_t)(col0 + ar + 32) * K + ac;

    float c[2][2][4] = {};
    const int ntiles = K >> 5;
    uint4 ab, wb0, wb1;

#define LOAD_AB(ko) do { \
    float4 u = *(const float4*)(Ap + (ko)); \
    float4 v = *(const float4*)(Ap + (ko) + 4); \
    float4 u2 = *(const float4*)(A2p + (ko)), u3 = *(const float4*)(A3p + (ko)); \
    float4 v2 = *(const float4*)(A2p + (ko) + 4), v3 = *(const float4*)(A3p + (ko) + 4); \
    u.x = (u.x + u2.x) * u3.x; u.y = (u.y + u2.y) * u3.y; \
    u.z = (u.z + u2.z) * u3.z; u.w = (u.w + u2.w) * u3.w; \
    v.x = (v.x + v2.x) * v3.x; v.y = (v.y + v2.y) * v3.y; \
    v.z = (v.z + v2.z) * v3.z; v.w = (v.w + v2.w) * v3.w; \
    ab = pack8(u, v); \
    { float4 xx = *(const float4*)(Wp0 + (ko)); \
      float4 yy = *(const float4*)(Wp0 + (ko) + 4); \
      wb0 = pack8(xx, yy); } \
    { float4 xx = *(const float4*)(Wp1 + (ko)); \
      float4 yy = *(const float4*)(Wp1 + (ko) + 4); \
      wb1 = pack8(xx, yy); } \
} while (0)

    LOAD_AB(0);
    for (int kt = 0; kt < ntiles; kt++) {
        __syncthreads();
        *(uint4*)&As[ar * SROW + (t & 3) * 4] = ab;
        *(uint4*)&Bs[ar * SROW + (t & 3) * 4] = wb0;
        *(uint4*)&Bs[(ar + 32) * SROW + (t & 3) * 4] = wb1;
        __syncthreads();
        if (kt + 1 < ntiles) LOAD_AB((kt + 1) * 32);
        #pragma unroll
        for (int k16 = 0; k16 < 2; k16++) {
            const int kb = k16 * 8;
            uint32_t afr[2][4], bfr[2][2];
            #pragma unroll
            for (int mi = 0; mi < 2; mi++) {
                int r = mi * 16 + g;
                afr[mi][0] = As[r * SROW + kb + tig];
                afr[mi][1] = As[(r + 8) * SROW + kb + tig];
                afr[mi][2] = As[r * SROW + kb + tig + 4];
                afr[mi][3] = As[(r + 8) * SROW + kb + tig + 4];
            }
            #pragma unroll
            for (int ni = 0; ni < 2; ni++) {
                int n = wn * 16 + ni * 8 + g;
                bfr[ni][0] = Bs[n * SROW + kb + tig];
                bfr[ni][1] = Bs[n * SROW + kb + tig + 4];
            }
            #pragma unroll
            for (int mi = 0; mi < 2; mi++)
                #pragma unroll
                for (int ni = 0; ni < 2; ni++)
                    mma_bf16(c[mi][ni], afr[mi][0], afr[mi][1], afr[mi][2],
                             afr[mi][3], bfr[ni][0], bfr[ni][1]);
        }
    }
#undef LOAD_AB

    #pragma unroll
    for (int mi = 0; mi < 2; mi++) {
        int r = row0 + mi * 16 + g;
        #pragma unroll
        for (int ni = 0; ni < 2; ni++) {
            int n = col0 + wn * 16 + ni * 8 + 2 * tig;
            float b0 = out_b[n], b1 = out_b[n + 1];
            *(float2*)&out[(size_t)r * N + n] =
                make_float2(c[mi][ni][0] + b0, c[mi][ni][1] + b1);
            *(float2*)&out[(size_t)(r + 8) * N + n] =
                make_float2(c[mi][ni][2] + b0, c[mi][ni][3] + b1);
        }
    }
}

// ---------------- launch ----------------
extern "C" void kernel_launch(void* const* d_in, const int* in_sizes, int n_in,
                              void* d_out, int out_size)
{
    const float* x      = (const float*)d_in[0];
    const float* mouth  = (const float*)d_in[1];
    const float* norm_w = (const float*)d_in[2];
    const float* inp_W  = (const float*)d_in[3];
    const float* inp_b  = (const float*)d_in[4];
    const float* out_W  = (const float*)d_in[5];
    const float* out_b  = (const float*)d_in[6];
    const float* Dlin_W = (const float*)d_in[7];
    const float* Dlin_b = (const float*)d_in[8];
    const float* conv_W = (const float*)d_in[9];
    const float* conv_b = (const float*)d_in[10];
    const float* fc1_W  = (const float*)d_in[11];
    const float* fc1_b  = (const float*)d_in[12];
    const float* fc2_W  = (const float*)d_in[13];
    const float* fc2_b  = (const float*)d_in[14];
    const float* A      = (const float*)d_in[15];

    const int SSM_SMEM = 2 * SSTAGE * 4;   // 46080 B
    cudaFuncSetAttribute(ssm_kernel,
                         cudaFuncAttributeMaxDynamicSharedMemorySize, SSM_SMEM);

    // 1) XNbf + E bf16 + weight bf16
    prep_kernel<<<672, 256>>>(x, mouth, norm_w, A, inp_W, Dlin_W, fc1_W, fc2_W);
    // 2) inp GEMM -> Pbf, res GEMM -> RES
    mega1_kernel<<<384, 128>>>(inp_b, Dlin_b);
    // 3) conv + silu -> XCbf
    conv_silu_kernel<<<128, 256>>>(conv_W, conv_b);
    // 4) delta GEMM -> DELTA, Bm GEMM -> BMbf
    mega2_kernel<<<320, 128>>>(fc1_b, fc2_b);
    // 5) ssm (4-slab GEMM + S2 + Horner + silu) -> XS
    ssm_kernel<<<dim3(D2 / 64, NROWS / 32), 128, SSM_SMEM>>>();
    // 6) out = ((XS_x + XS_m) * RES) @ out_W^T + out_b
    out_kernel<<<dim3(Dm / 64, HROWS / 32), 128>>>(out_W, out_b, (float*)d_out);
}